// round 1
// baseline (speedup 1.0000x reference)
#include <cuda_runtime.h>
#include <cuda_bf16.h>
#include <cstdint>

// ---------------- problem constants (gpt-small) ----------------
#define LAYERS 8
#define HEADS  8
#define CDIM   256
#define VDIM   128
#define TSEQ   1024
#define BATCH  32
#define DHEAD  32
#define FFDIM  1024
#define NTOK   (BATCH * TSEQ)        // 32768

// ---------------- scratch (static device allocations; no cudaMalloc) ----
__device__ float g_x  [(size_t)NTOK * CDIM];    // residual stream
__device__ float g_h  [(size_t)NTOK * CDIM];    // layernorm output
__device__ float g_qkv[(size_t)NTOK * 3 * CDIM];
__device__ float g_y  [(size_t)NTOK * CDIM];    // attention output
__device__ float g_ff [(size_t)NTOK * FFDIM];

// ---------------- helpers ----------------
__device__ __forceinline__ float warp_sum(float v) {
    #pragma unroll
    for (int o = 16; o; o >>= 1) v += __shfl_xor_sync(0xFFFFFFFFu, v, o);
    return v;
}

// FMA-only 2^x (avoids MUFU.EX2 pressure in softmax).
// Valid for x >= ~-120; Cephes minimax poly on f in [-0.5, 0.5].
__device__ __forceinline__ float fast_exp2(float x) {
    x = fmaxf(x, -120.0f);
    float r = x + 12582912.0f;           // 1.5 * 2^23: round-to-nearest int
    float n = r - 12582912.0f;
    float f = x - n;                     // [-0.5, 0.5]
    float p =          1.535336188319500e-4f;
    p = fmaf(p, f,     1.339887440266574e-3f);
    p = fmaf(p, f,     9.618437357674640e-3f);
    p = fmaf(p, f,     5.550332471162809e-2f);
    p = fmaf(p, f,     2.402264791363012e-1f);
    p = fmaf(p, f,     6.931472028550421e-1f);
    p = fmaf(p, f,     1.0f);
    int e = __float_as_int(r) << 23;     // integer n lands in exponent field
    return __int_as_float(__float_as_int(p) + e);
}

__device__ __forceinline__ float gelu_f(float x) {
    float x3 = x * x * x;
    float u  = 0.7978845608028654f * fmaf(0.044715f, x3, x);
    float t  = tanhf(u);
    return 0.5f * x * (1.0f + t);
}

// ---------------- embedding: x = tok_emb[idx] + pos_emb ----------------
__global__ void embed_kernel(const int* __restrict__ idx,
                             const float* __restrict__ tok,
                             const float* __restrict__ pos,
                             float* __restrict__ x) {
    int i = blockIdx.x * blockDim.x + threadIdx.x;
    if (i >= NTOK * CDIM) return;
    int row = i >> 8;          // token index (b*T + t)
    int c   = i & (CDIM - 1);
    int t   = row & (TSEQ - 1);
    x[i] = tok[(size_t)idx[row] * CDIM + c] + pos[(size_t)t * CDIM + c];
}

// ---------------- layernorm over C=256, one row per block (256 thr) ----
__global__ void ln_kernel(const float* __restrict__ x,
                          const float* __restrict__ g,
                          const float* __restrict__ b,
                          float* __restrict__ out) {
    int row = blockIdx.x;
    int c   = threadIdx.x;
    float v = x[(size_t)row * CDIM + c];
    float s1 = warp_sum(v);
    float s2 = warp_sum(v * v);
    __shared__ float sh1[8], sh2[8];
    int w = c >> 5, lane = c & 31;
    if (lane == 0) { sh1[w] = s1; sh2[w] = s2; }
    __syncthreads();
    float t1 = 0.f, t2 = 0.f;
    #pragma unroll
    for (int i = 0; i < 8; i++) { t1 += sh1[i]; t2 += sh2[i]; }
    float mean = t1 * (1.0f / CDIM);
    float var  = t2 * (1.0f / CDIM) - mean * mean;
    float rstd = rsqrtf(var + 1e-5f);
    out[(size_t)row * CDIM + c] = (v - mean) * rstd * g[c] + b[c];
}

// ---------------- tiled SGEMM: C[M,N] = A[M,K] @ B[K,N] (+epilogue) ----
// MODE 0: plain   1: +bias   2: +bias +residual R   3: +bias, GELU
#define BM 128
#define BN 64
#define BK 16
#define TM 8
#define TN 4

template<int MODE>
__global__ __launch_bounds__(256) void gemm_kernel(
    const float* __restrict__ A, const float* __restrict__ B,
    const float* __restrict__ bias, const float* __restrict__ R,
    float* __restrict__ C, int M, int N, int K)
{
    __shared__ float As[BK][BM + 4];
    __shared__ float Bs[BK][BN + 4];

    int block_m = blockIdx.y * BM;
    int block_n = blockIdx.x * BN;
    int tid = threadIdx.x;
    int tx = tid & 15;         // 16 col-groups of 4
    int ty = tid >> 4;         // 16 row-groups of 8

    float acc[TM][TN];
    #pragma unroll
    for (int i = 0; i < TM; i++)
        #pragma unroll
        for (int j = 0; j < TN; j++) acc[i][j] = 0.f;

    for (int k0 = 0; k0 < K; k0 += BK) {
        // A tile 128x16: 512 float4 loads, 2 per thread, scattered into As[k][m]
        #pragma unroll
        for (int i = 0; i < 2; i++) {
            int idx = tid + i * 256;
            int row = idx >> 2;
            int kq  = (idx & 3) * 4;
            float4 v = *(const float4*)(A + (size_t)(block_m + row) * K + k0 + kq);
            As[kq + 0][row] = v.x; As[kq + 1][row] = v.y;
            As[kq + 2][row] = v.z; As[kq + 3][row] = v.w;
        }
        // B tile 16x64: 256 float4, 1 per thread, direct layout
        {
            int row = tid >> 4;
            int nc  = (tid & 15) * 4;
            *(float4*)&Bs[row][nc] =
                *(const float4*)(B + (size_t)(k0 + row) * N + block_n + nc);
        }
        __syncthreads();

        #pragma unroll
        for (int kk = 0; kk < BK; kk++) {
            float4 a0 = *(float4*)&As[kk][ty * TM];
            float4 a1 = *(float4*)&As[kk][ty * TM + 4];
            float4 bv = *(float4*)&Bs[kk][tx * TN];
            float a[TM] = {a0.x, a0.y, a0.z, a0.w, a1.x, a1.y, a1.z, a1.w};
            float bb[TN] = {bv.x, bv.y, bv.z, bv.w};
            #pragma unroll
            for (int i = 0; i < TM; i++)
                #pragma unroll
                for (int j = 0; j < TN; j++)
                    acc[i][j] = fmaf(a[i], bb[j], acc[i][j]);
        }
        __syncthreads();
    }

    // epilogue, vectorized float4 along N
    int n = block_n + tx * TN;
    float4 bvec = make_float4(0.f, 0.f, 0.f, 0.f);
    if (MODE >= 1) bvec = *(const float4*)(bias + n);
    #pragma unroll
    for (int i = 0; i < TM; i++) {
        int m = block_m + ty * TM + i;
        float4 v = make_float4(acc[i][0] + bvec.x, acc[i][1] + bvec.y,
                               acc[i][2] + bvec.z, acc[i][3] + bvec.w);
        if (MODE == 2) {
            float4 rr = *(const float4*)(R + (size_t)m * N + n);
            v.x += rr.x; v.y += rr.y; v.z += rr.z; v.w += rr.w;
        }
        if (MODE == 3) {
            v.x = gelu_f(v.x); v.y = gelu_f(v.y);
            v.z = gelu_f(v.z); v.w = gelu_f(v.w);
        }
        *(float4*)(C + (size_t)m * N + n) = v;
    }
}

// ---------------- causal attention, flash-style, 1 thread = 1 query ----
#define QT 128
#define KT 64
#define LOG2E 1.4426950408889634f

__global__ __launch_bounds__(QT) void attn_kernel(const float* __restrict__ qkv,
                                                  float* __restrict__ y) {
    int bh = blockIdx.y;
    int b  = bh >> 3;
    int h  = bh & 7;
    int qt = blockIdx.x;
    int tid = threadIdx.x;
    int t = qt * QT + tid;                      // query index in sequence

    const float qscale = 0.17677669529663687f * LOG2E;  // 1/sqrt(32) * log2(e)
    const float* qp = qkv + ((size_t)(b * TSEQ + t) * (3 * CDIM)) + h * DHEAD;
    float q[DHEAD];
    #pragma unroll
    for (int d = 0; d < DHEAD; d++) q[d] = qp[d] * qscale;

    float o[DHEAD];
    #pragma unroll
    for (int d = 0; d < DHEAD; d++) o[d] = 0.f;
    float m = -1e30f, l = 0.f;

    __shared__ float Ks[KT][DHEAD];
    __shared__ float Vs[KT][DHEAD];

    int ntiles = qt * 2 + 2;                    // covers keys 0..(qt*128+127)
    for (int kb = 0; kb < ntiles; kb++) {
        int j0 = kb * KT;
        __syncthreads();
        #pragma unroll
        for (int i = 0; i < 4; i++) {
            int idx = tid + i * QT;             // 0..511
            int r = idx >> 3;
            int c4 = (idx & 7) * 4;
            const float* kp = qkv + ((size_t)(b * TSEQ + j0 + r) * (3 * CDIM))
                              + CDIM + h * DHEAD + c4;
            *(float4*)&Ks[r][c4] = *(const float4*)kp;
            *(float4*)&Vs[r][c4] = *(const float4*)(kp + CDIM);
        }
        __syncthreads();

        int jmax = min(KT, t - j0 + 1);         // causal: keys j0..j0+jmax-1
        for (int jj = 0; jj < jmax; jj++) {
            float s = 0.f;
            #pragma unroll
            for (int d = 0; d < DHEAD; d++) s = fmaf(q[d], Ks[jj][d], s);
            if (s > m) {
                float corr = fast_exp2(m - s);
                l *= corr;
                #pragma unroll
                for (int d = 0; d < DHEAD; d++) o[d] *= corr;
                m = s;
            }
            float p = fast_exp2(s - m);
            l += p;
            #pragma unroll
            for (int d = 0; d < DHEAD; d++) o[d] = fmaf(p, Vs[jj][d], o[d]);
        }
    }

    float inv = 1.0f / l;
    float* yp = y + ((size_t)(b * TSEQ + t) * CDIM) + h * DHEAD;
    #pragma unroll
    for (int d = 0; d < DHEAD; d += 4) {
        float4 v = make_float4(o[d] * inv, o[d+1] * inv, o[d+2] * inv, o[d+3] * inv);
        *(float4*)(yp + d) = v;
    }
}

// ---------------- host orchestration (graph-capturable) ----------------
extern "C" void kernel_launch(void* const* d_in, const int* in_sizes, int n_in,
                              void* d_out, int out_size) {
    (void)in_sizes; (void)n_in; (void)out_size;
    const int*   idx   = (const int*)  d_in[0];
    const float* tok   = (const float*)d_in[1];
    const float* pos   = (const float*)d_in[2];
    const float* ln1g  = (const float*)d_in[3];
    const float* ln1b  = (const float*)d_in[4];
    const float* wqkv  = (const float*)d_in[5];
    const float* bqkv  = (const float*)d_in[6];
    const float* wo    = (const float*)d_in[7];
    const float* bo    = (const float*)d_in[8];
    const float* ln2g  = (const float*)d_in[9];
    const float* ln2b  = (const float*)d_in[10];
    const float* wfc   = (const float*)d_in[11];
    const float* bfc   = (const float*)d_in[12];
    const float* wpr   = (const float*)d_in[13];
    const float* bpr   = (const float*)d_in[14];
    const float* lnfg  = (const float*)d_in[15];
    const float* lnfb  = (const float*)d_in[16];
    const float* wlm   = (const float*)d_in[17];
    float* out = (float*)d_out;

    float *x, *h, *qkvb, *y, *ff;
    cudaGetSymbolAddress((void**)&x,    g_x);
    cudaGetSymbolAddress((void**)&h,    g_h);
    cudaGetSymbolAddress((void**)&qkvb, g_qkv);
    cudaGetSymbolAddress((void**)&y,    g_y);
    cudaGetSymbolAddress((void**)&ff,   g_ff);

    dim3 gemm_blk(256);
    dim3 grid_qkv (3 * CDIM / BN, NTOK / BM);   // N=768
    dim3 grid_proj(CDIM / BN,     NTOK / BM);   // N=256
    dim3 grid_fc  (FFDIM / BN,    NTOK / BM);   // N=1024
    dim3 grid_lm  (VDIM / BN,     NTOK / BM);   // N=128
    dim3 grid_att (TSEQ / QT, BATCH * HEADS);

    embed_kernel<<<(NTOK * CDIM + 255) / 256, 256>>>(idx, tok, pos, x);

    for (int l = 0; l < LAYERS; l++) {
        ln_kernel<<<NTOK, 256>>>(x, ln1g + l * CDIM, ln1b + l * CDIM, h);
        gemm_kernel<1><<<grid_qkv, gemm_blk>>>(
            h, wqkv + (size_t)l * CDIM * 3 * CDIM, bqkv + (size_t)l * 3 * CDIM,
            nullptr, qkvb, NTOK, 3 * CDIM, CDIM);
        attn_kernel<<<grid_att, QT>>>(qkvb, y);
        gemm_kernel<2><<<grid_proj, gemm_blk>>>(
            y, wo + (size_t)l * CDIM * CDIM, bo + (size_t)l * CDIM,
            x, x, NTOK, CDIM, CDIM);
        ln_kernel<<<NTOK, 256>>>(x, ln2g + l * CDIM, ln2b + l * CDIM, h);
        gemm_kernel<3><<<grid_fc, gemm_blk>>>(
            h, wfc + (size_t)l * CDIM * FFDIM, bfc + (size_t)l * FFDIM,
            nullptr, ff, NTOK, FFDIM, CDIM);
        gemm_kernel<2><<<grid_proj, gemm_blk>>>(
            ff, wpr + (size_t)l * FFDIM * CDIM, bpr + (size_t)l * CDIM,
            x, x, NTOK, CDIM, FFDIM);
    }

    ln_kernel<<<NTOK, 256>>>(x, lnfg, lnfb, h);
    gemm_kernel<0><<<grid_lm, gemm_blk>>>(
        h, wlm, nullptr, nullptr, out, NTOK, VDIM, CDIM);
}

// round 3
// speedup vs baseline: 1.4357x; 1.4357x over previous
#include <cuda_runtime.h>
#include <cuda_bf16.h>
#include <cstdint>

// ---------------- problem constants (gpt-small) ----------------
#define LAYERS 8
#define HEADS  8
#define CDIM   256
#define VDIM   128
#define TSEQ   1024
#define BATCH  32
#define DHEAD  32
#define FFDIM  1024
#define NTOK   (BATCH * TSEQ)        // 32768

// ---------------- scratch (static device allocations) ----------------
__device__ float g_x  [(size_t)NTOK * CDIM];          // residual stream (fp32)
__device__ float g_qkv[(size_t)NTOK * 3 * CDIM];      // qkv (fp32) for attention
__device__ __nv_bfloat16 g_hh[(size_t)NTOK * CDIM];   // LN out hi
__device__ __nv_bfloat16 g_hl[(size_t)NTOK * CDIM];   // LN out lo
__device__ __nv_bfloat16 g_yh[(size_t)NTOK * CDIM];   // attn out hi
__device__ __nv_bfloat16 g_yl[(size_t)NTOK * CDIM];   // attn out lo
__device__ __nv_bfloat16 g_gh[(size_t)NTOK * FFDIM];  // gelu out hi
__device__ __nv_bfloat16 g_gl[(size_t)NTOK * FFDIM];  // gelu out lo
// transposed/split weights [N,K] bf16 hi/lo
__device__ __nv_bfloat16 g_wqkvT_h[(size_t)LAYERS * 3 * CDIM * CDIM];
__device__ __nv_bfloat16 g_wqkvT_l[(size_t)LAYERS * 3 * CDIM * CDIM];
__device__ __nv_bfloat16 g_woT_h  [(size_t)LAYERS * CDIM * CDIM];
__device__ __nv_bfloat16 g_woT_l  [(size_t)LAYERS * CDIM * CDIM];
__device__ __nv_bfloat16 g_wfcT_h [(size_t)LAYERS * FFDIM * CDIM];
__device__ __nv_bfloat16 g_wfcT_l [(size_t)LAYERS * FFDIM * CDIM];
__device__ __nv_bfloat16 g_wprT_h [(size_t)LAYERS * CDIM * FFDIM];
__device__ __nv_bfloat16 g_wprT_l [(size_t)LAYERS * CDIM * FFDIM];
__device__ __nv_bfloat16 g_wlmT_h [(size_t)VDIM * CDIM];
__device__ __nv_bfloat16 g_wlmT_l [(size_t)VDIM * CDIM];

// ---------------- low-level helpers ----------------
__device__ __forceinline__ uint32_t smem_to_u32(const void* p) {
    uint32_t a;
    asm("{ .reg .u64 t; cvta.to.shared.u64 t, %1; cvt.u32.u64 %0, t; }" : "=r"(a) : "l"(p));
    return a;
}
__device__ __forceinline__ void cp16(uint32_t s, const void* g) {
    asm volatile("cp.async.ca.shared.global [%0], [%1], 16;" :: "r"(s), "l"(g) : "memory");
}
#define CP_COMMIT() asm volatile("cp.async.commit_group;" ::: "memory")
#define CP_WAIT1()  asm volatile("cp.async.wait_group 1;" ::: "memory")
#define CP_WAIT0()  asm volatile("cp.async.wait_group 0;" ::: "memory")

__device__ __forceinline__ void ldm4(uint32_t a, uint32_t& r0, uint32_t& r1,
                                     uint32_t& r2, uint32_t& r3) {
    asm volatile("ldmatrix.sync.aligned.m8n8.x4.shared.b16 {%0,%1,%2,%3}, [%4];"
        : "=r"(r0), "=r"(r1), "=r"(r2), "=r"(r3) : "r"(a));
}
__device__ __forceinline__ void mma16816(float* c, const uint32_t* a, const uint32_t* b) {
    asm volatile("mma.sync.aligned.m16n8k16.row.col.f32.bf16.bf16.f32 "
        "{%0,%1,%2,%3}, {%4,%5,%6,%7}, {%8,%9}, {%0,%1,%2,%3};"
        : "+f"(c[0]), "+f"(c[1]), "+f"(c[2]), "+f"(c[3])
        : "r"(a[0]), "r"(a[1]), "r"(a[2]), "r"(a[3]), "r"(b[0]), "r"(b[1]));
}

// packed f32x2 (B300: FFMA2 only reachable via PTX fma.rn.f32x2)
__device__ __forceinline__ uint64_t pack2(float lo, float hi) {
    uint64_t r; asm("mov.b64 %0, {%1, %2};" : "=l"(r) : "f"(lo), "f"(hi)); return r;
}
__device__ __forceinline__ void unpack2(uint64_t v, float& lo, float& hi) {
    asm("mov.b64 {%0, %1}, %2;" : "=f"(lo), "=f"(hi) : "l"(v));
}
__device__ __forceinline__ uint64_t fma2(uint64_t a, uint64_t b, uint64_t c) {
    uint64_t d; asm("fma.rn.f32x2 %0, %1, %2, %3;" : "=l"(d) : "l"(a), "l"(b), "l"(c)); return d;
}
__device__ __forceinline__ uint64_t add2(uint64_t a, uint64_t b) {
    uint64_t d; asm("add.rn.f32x2 %0, %1, %2;" : "=l"(d) : "l"(a), "l"(b)); return d;
}
__device__ __forceinline__ uint64_t mul2(uint64_t a, uint64_t b) {
    uint64_t d; asm("mul.rn.f32x2 %0, %1, %2;" : "=l"(d) : "l"(a), "l"(b)); return d;
}

// ---------------- math helpers ----------------
__device__ __forceinline__ float warp_sum(float v) {
    #pragma unroll
    for (int o = 16; o; o >>= 1) v += __shfl_xor_sync(0xFFFFFFFFu, v, o);
    return v;
}
__device__ __forceinline__ float fast_exp2(float x) {
    x = fmaxf(x, -120.0f);
    float r = x + 12582912.0f;
    float f = x - (r - 12582912.0f);
    float p =          1.535336188319500e-4f;
    p = fmaf(p, f,     1.339887440266574e-3f);
    p = fmaf(p, f,     9.618437357674640e-3f);
    p = fmaf(p, f,     5.550332471162809e-2f);
    p = fmaf(p, f,     2.402264791363012e-1f);
    p = fmaf(p, f,     6.931472028550421e-1f);
    p = fmaf(p, f,     1.0f);
    return __int_as_float(__float_as_int(p) + (__float_as_int(r) << 23));
}
__device__ __forceinline__ float gelu_f(float x) {
    float x3 = x * x * x;
    float u  = 0.7978845608028654f * fmaf(0.044715f, x3, x);
    return 0.5f * x * (1.0f + tanhf(u));
}
__device__ __forceinline__ void bf16split(float v, __nv_bfloat16& h, __nv_bfloat16& l) {
    h = __float2bfloat16(v);
    l = __float2bfloat16(v - __bfloat162float(h));
}

// ---------------- weight transpose + bf16 hi/lo split ----------------
__global__ void wsplit_kernel(const float* __restrict__ W,
                              __nv_bfloat16* __restrict__ Th,
                              __nv_bfloat16* __restrict__ Tl,
                              int K, int N) {
    __shared__ float t[32][33];
    int nx = blockIdx.x * 32, kx = blockIdx.y * 32;
    #pragma unroll
    for (int i = 0; i < 4; i++) {
        int k = kx + threadIdx.y + i * 8;
        t[threadIdx.y + i * 8][threadIdx.x] = W[(size_t)k * N + nx + threadIdx.x];
    }
    __syncthreads();
    #pragma unroll
    for (int i = 0; i < 4; i++) {
        int n = nx + threadIdx.y + i * 8;
        int k = kx + threadIdx.x;
        float v = t[threadIdx.x][threadIdx.y + i * 8];
        __nv_bfloat16 h, l; bf16split(v, h, l);
        Th[(size_t)n * K + k] = h;
        Tl[(size_t)n * K + k] = l;
    }
}

// ---------------- embedding ----------------
__global__ void embed_kernel(const int* __restrict__ idx,
                             const float* __restrict__ tok,
                             const float* __restrict__ pos,
                             float* __restrict__ x) {
    int i = blockIdx.x * blockDim.x + threadIdx.x;
    if (i >= NTOK * CDIM) return;
    int row = i >> 8;
    int c   = i & (CDIM - 1);
    int t   = row & (TSEQ - 1);
    x[i] = tok[(size_t)idx[row] * CDIM + c] + pos[(size_t)t * CDIM + c];
}

// ---------------- layernorm -> bf16 hi/lo pair ----------------
__global__ void ln_kernel(const float* __restrict__ x,
                          const float* __restrict__ g,
                          const float* __restrict__ b,
                          __nv_bfloat16* __restrict__ oh,
                          __nv_bfloat16* __restrict__ ol) {
    int row = blockIdx.x;
    int c   = threadIdx.x;
    float v = x[(size_t)row * CDIM + c];
    float s1 = warp_sum(v);
    float s2 = warp_sum(v * v);
    __shared__ float sh1[8], sh2[8];
    int w = c >> 5, lane = c & 31;
    if (lane == 0) { sh1[w] = s1; sh2[w] = s2; }
    __syncthreads();
    float t1 = 0.f, t2 = 0.f;
    #pragma unroll
    for (int i = 0; i < 8; i++) { t1 += sh1[i]; t2 += sh2[i]; }
    float mean = t1 * (1.0f / CDIM);
    float var  = t2 * (1.0f / CDIM) - mean * mean;
    float rstd = rsqrtf(var + 1e-5f);
    float o = (v - mean) * rstd * g[c] + b[c];
    __nv_bfloat16 h, l; bf16split(o, h, l);
    oh[(size_t)row * CDIM + c] = h;
    ol[(size_t)row * CDIM + c] = l;
}

// ---------------- mma.sync bf16x3 GEMM ----------------
// D[M,N] = A[M,K] @ Bt[N,K]^T.  A/B are bf16 hi/lo pairs; fp32 accumulators.
// Block 128x128, BK=32, 256 threads = 8 warps (warp tile 32x64), cp.async 2-stage.
// MODE 0: plain fp32   1: +bias fp32   2: +bias +residual fp32
// MODE 3: +bias, GELU -> bf16 hi/lo outputs
#define GBM 128
#define GBN 128
#define GBK 32
#define ROWB 80                         // smem row pitch: 64B data + 16B pad
#define TILE_B (128 * ROWB)             // 10240 bytes per tile
#define STAGE_B (4 * TILE_B)            // Ah, Al, Bh, Bl
#define GSMEM (2 * STAGE_B)             // 81920 bytes

template<int MODE>
__global__ __launch_bounds__(256, 1)
void gemm_mma(const __nv_bfloat16* __restrict__ Ah, const __nv_bfloat16* __restrict__ Al,
              const __nv_bfloat16* __restrict__ Bh, const __nv_bfloat16* __restrict__ Bl,
              const float* __restrict__ bias, const float* __restrict__ res,
              float* __restrict__ outF,
              __nv_bfloat16* __restrict__ outH, __nv_bfloat16* __restrict__ outL,
              int K, int No)
{
    extern __shared__ char smem[];
    uint32_t sU = smem_to_u32(smem);
    int tid  = threadIdx.x;
    int wid  = tid >> 5, lane = tid & 31;
    int warp_m = wid & 3, warp_n = wid >> 2;
    int m0 = blockIdx.y * GBM, n0 = blockIdx.x * GBN;

    float C[2][8][4];
    #pragma unroll
    for (int mt = 0; mt < 2; mt++)
        #pragma unroll
        for (int nt = 0; nt < 8; nt++)
            #pragma unroll
            for (int k = 0; k < 4; k++) C[mt][nt][k] = 0.f;

    // per-thread load coords: 512 16B-chunks per tile, 2 per thread
    int lr0 = tid >> 2,  lc0 = (tid & 3);
    int lr1 = (tid + 256) >> 2, lc1 = ((tid + 256) & 3);

    int nch = K >> 5;
    // ---- stage loader ----
    auto load_stage = [&](int ch, int buf) {
        int k0 = ch * GBK;
        uint32_t sb = sU + buf * STAGE_B;
        {
            uint32_t so = lr0 * ROWB + lc0 * 16;
            const __nv_bfloat16* gA = Ah + (size_t)(m0 + lr0) * K + k0 + lc0 * 8;
            const __nv_bfloat16* gAl = Al + (size_t)(m0 + lr0) * K + k0 + lc0 * 8;
            const __nv_bfloat16* gB = Bh + (size_t)(n0 + lr0) * K + k0 + lc0 * 8;
            const __nv_bfloat16* gBl = Bl + (size_t)(n0 + lr0) * K + k0 + lc0 * 8;
            cp16(sb + so, gA);
            cp16(sb + TILE_B + so, gAl);
            cp16(sb + 2 * TILE_B + so, gB);
            cp16(sb + 3 * TILE_B + so, gBl);
        }
        {
            uint32_t so = lr1 * ROWB + lc1 * 16;
            const __nv_bfloat16* gA = Ah + (size_t)(m0 + lr1) * K + k0 + lc1 * 8;
            const __nv_bfloat16* gAl = Al + (size_t)(m0 + lr1) * K + k0 + lc1 * 8;
            const __nv_bfloat16* gB = Bh + (size_t)(n0 + lr1) * K + k0 + lc1 * 8;
            const __nv_bfloat16* gBl = Bl + (size_t)(n0 + lr1) * K + k0 + lc1 * 8;
            cp16(sb + so, gA);
            cp16(sb + TILE_B + so, gAl);
            cp16(sb + 2 * TILE_B + so, gB);
            cp16(sb + 3 * TILE_B + so, gBl);
        }
    };

    load_stage(0, 0);
    CP_COMMIT();

    int rin = lane & 7;
    int amat = lane >> 3;               // A: mat index 0..3
    int bnt  = (lane >> 4) & 1;         // B: n-subtile within group
    int bkh  = (lane >> 3) & 1;         // B: k-half

    for (int ch = 0; ch < nch; ch++) {
        int buf = ch & 1;
        if (ch + 1 < nch) load_stage(ch + 1, buf ^ 1);
        CP_COMMIT();
        CP_WAIT1();
        __syncthreads();

        uint32_t sA  = sU + buf * STAGE_B;
        uint32_t sAl = sA + TILE_B;
        uint32_t sBh = sA + 2 * TILE_B;
        uint32_t sBl = sA + 3 * TILE_B;

        #pragma unroll
        for (int s = 0; s < 2; s++) {
            uint32_t ah[2][4], al[2][4], bh[8][2], bl[8][2];
            #pragma unroll
            for (int mt = 0; mt < 2; mt++) {
                int row = warp_m * 32 + mt * 16 + (amat & 1) * 8 + rin;
                uint32_t off = row * ROWB + (amat >> 1) * 16 + s * 32;
                ldm4(sA  + off, ah[mt][0], ah[mt][1], ah[mt][2], ah[mt][3]);
                ldm4(sAl + off, al[mt][0], al[mt][1], al[mt][2], al[mt][3]);
            }
            #pragma unroll
            for (int ng = 0; ng < 4; ng++) {
                int row = warp_n * 64 + ng * 16 + bnt * 8 + rin;
                uint32_t off = row * ROWB + bkh * 16 + s * 32;
                ldm4(sBh + off, bh[2*ng][0], bh[2*ng][1], bh[2*ng+1][0], bh[2*ng+1][1]);
                ldm4(sBl + off, bl[2*ng][0], bl[2*ng][1], bl[2*ng+1][0], bl[2*ng+1][1]);
            }
            #pragma unroll
            for (int mt = 0; mt < 2; mt++)
                #pragma unroll
                for (int nt = 0; nt < 8; nt++) {
                    mma16816(C[mt][nt], ah[mt], bh[nt]);
                    mma16816(C[mt][nt], ah[mt], bl[nt]);
                    mma16816(C[mt][nt], al[mt], bh[nt]);
                }
        }
        __syncthreads();
    }
    CP_WAIT0();

    // ---- epilogue ----
    int rbase = m0 + warp_m * 32;
    int cbase = n0 + warp_n * 64;
    #pragma unroll
    for (int mt = 0; mt < 2; mt++) {
        #pragma unroll
        for (int nt = 0; nt < 8; nt++) {
            int row = rbase + mt * 16 + (lane >> 2);
            int col = cbase + nt * 8 + (lane & 3) * 2;
            const float* c = C[mt][nt];
            float2 b2 = make_float2(0.f, 0.f);
            if (MODE >= 1) b2 = *(const float2*)(bias + col);
            if (MODE == 3) {
                float g0 = gelu_f(c[0] + b2.x), g1 = gelu_f(c[1] + b2.y);
                float g2 = gelu_f(c[2] + b2.x), g3 = gelu_f(c[3] + b2.y);
                __nv_bfloat16 h0, l0, h1, l1;
                bf16split(g0, h0, l0); bf16split(g1, h1, l1);
                *(__nv_bfloat162*)(outH + (size_t)row * No + col) = __nv_bfloat162(h0, h1);
                *(__nv_bfloat162*)(outL + (size_t)row * No + col) = __nv_bfloat162(l0, l1);
                bf16split(g2, h0, l0); bf16split(g3, h1, l1);
                *(__nv_bfloat162*)(outH + (size_t)(row + 8) * No + col) = __nv_bfloat162(h0, h1);
                *(__nv_bfloat162*)(outL + (size_t)(row + 8) * No + col) = __nv_bfloat162(l0, l1);
            } else {
                float2 v0 = make_float2(c[0] + b2.x, c[1] + b2.y);
                float2 v1 = make_float2(c[2] + b2.x, c[3] + b2.y);
                if (MODE == 2) {
                    float2 r0 = *(const float2*)(res + (size_t)row * No + col);
                    float2 r1 = *(const float2*)(res + (size_t)(row + 8) * No + col);
                    v0.x += r0.x; v0.y += r0.y; v1.x += r1.x; v1.y += r1.y;
                }
                *(float2*)(outF + (size_t)row * No + col) = v0;
                *(float2*)(outF + (size_t)(row + 8) * No + col) = v1;
            }
        }
    }
}

// ---------------- causal attention, packed f32x2 math ----------------
#define QT 128
#define KT 128
#define LOG2E 1.4426950408889634f

__global__ __launch_bounds__(QT) void attn_kernel(const float* __restrict__ qkv,
                                                  __nv_bfloat16* __restrict__ yh,
                                                  __nv_bfloat16* __restrict__ yl) {
    __shared__ uint64_t Ks2[KT][16];
    __shared__ uint64_t Vs2[KT][16];
    int bh_ = blockIdx.y;
    int b = bh_ >> 3, h = bh_ & 7;
    int tid = threadIdx.x;
    int t = blockIdx.x * QT + tid;

    const float qscale = 0.17677669529663687f * LOG2E;
    const float* qp = qkv + ((size_t)(b * TSEQ + t) * (3 * CDIM)) + h * DHEAD;
    uint64_t q2[16];
    #pragma unroll
    for (int i = 0; i < 16; i++)
        q2[i] = pack2(qp[2 * i] * qscale, qp[2 * i + 1] * qscale);

    uint64_t o2[16];
    #pragma unroll
    for (int i = 0; i < 16; i++) o2[i] = 0ull;
    float m = -1e30f, l = 0.f;

    int ntiles = blockIdx.x + 1;
    for (int kb = 0; kb < ntiles; kb++) {
        int j0 = kb * KT;
        __syncthreads();
        #pragma unroll
        for (int i = 0; i < 8; i++) {
            int idx = tid + i * QT;             // 0..1023
            int r = idx >> 3;
            int c4 = (idx & 7) * 4;             // float index within row
            const float* kp = qkv + ((size_t)(b * TSEQ + j0 + r) * (3 * CDIM))
                              + CDIM + h * DHEAD + c4;
            *(float4*)((char*)Ks2[r] + c4 * 4) = *(const float4*)kp;
            *(float4*)((char*)Vs2[r] + c4 * 4) = *(const float4*)(kp + CDIM);
        }
        __syncthreads();

        int jmax = min(KT, t - j0 + 1);
        for (int jj = 0; jj < jmax; jj++) {
            const uint64_t* kr = Ks2[jj];
            uint64_t a0 = 0, a1 = 0, a2 = 0, a3 = 0;
            #pragma unroll
            for (int i = 0; i < 16; i += 4) {
                a0 = fma2(q2[i],     kr[i],     a0);
                a1 = fma2(q2[i + 1], kr[i + 1], a1);
                a2 = fma2(q2[i + 2], kr[i + 2], a2);
                a3 = fma2(q2[i + 3], kr[i + 3], a3);
            }
            a0 = add2(a0, a1); a2 = add2(a2, a3); a0 = add2(a0, a2);
            float slo, shi; unpack2(a0, slo, shi);
            float s = slo + shi;

            if (s > m) {
                float corr = fast_exp2(m - s);
                l *= corr;
                uint64_t c2p = pack2(corr, corr);
                #pragma unroll
                for (int i = 0; i < 16; i++) o2[i] = mul2(c2p, o2[i]);
                m = s;
            }
            float p = fast_exp2(s - m);
            l += p;
            uint64_t p2 = pack2(p, p);
            const uint64_t* vr = Vs2[jj];
            #pragma unroll
            for (int i = 0; i < 16; i++) o2[i] = fma2(p2, vr[i], o2[i]);
        }
    }

    float inv = 1.0f / l;
    size_t base = (size_t)(b * TSEQ + t) * CDIM + h * DHEAD;
    #pragma unroll
    for (int i = 0; i < 16; i++) {
        float lo, hi; unpack2(o2[i], lo, hi);
        __nv_bfloat16 h0, l0, h1, l1;
        bf16split(lo * inv, h0, l0);
        bf16split(hi * inv, h1, l1);
        *(__nv_bfloat162*)(yh + base + 2 * i) = __nv_bfloat162(h0, h1);
        *(__nv_bfloat162*)(yl + base + 2 * i) = __nv_bfloat162(l0, l1);
    }
}

// ---------------- host orchestration (graph-capturable) ----------------
extern "C" void kernel_launch(void* const* d_in, const int* in_sizes, int n_in,
                              void* d_out, int out_size) {
    (void)in_sizes; (void)n_in; (void)out_size;
    const int*   idx   = (const int*)  d_in[0];
    const float* tok   = (const float*)d_in[1];
    const float* pos   = (const float*)d_in[2];
    const float* ln1g  = (const float*)d_in[3];
    const float* ln1b  = (const float*)d_in[4];
    const float* wqkv  = (const float*)d_in[5];
    const float* bqkv  = (const float*)d_in[6];
    const float* wo    = (const float*)d_in[7];
    const float* bo    = (const float*)d_in[8];
    const float* ln2g  = (const float*)d_in[9];
    const float* ln2b  = (const float*)d_in[10];
    const float* wfc   = (const float*)d_in[11];
    const float* bfc   = (const float*)d_in[12];
    const float* wpr   = (const float*)d_in[13];
    const float* bpr   = (const float*)d_in[14];
    const float* lnfg  = (const float*)d_in[15];
    const float* lnfb  = (const float*)d_in[16];
    const float* wlm   = (const float*)d_in[17];
    float* out = (float*)d_out;

    float *x, *qkvb;
    __nv_bfloat16 *hh, *hl, *yh, *yl, *gh, *gl;
    __nv_bfloat16 *wqkvTh, *wqkvTl, *woTh, *woTl, *wfcTh, *wfcTl, *wprTh, *wprTl, *wlmTh, *wlmTl;
    cudaGetSymbolAddress((void**)&x,    g_x);
    cudaGetSymbolAddress((void**)&qkvb, g_qkv);
    cudaGetSymbolAddress((void**)&hh,   g_hh);
    cudaGetSymbolAddress((void**)&hl,   g_hl);
    cudaGetSymbolAddress((void**)&yh,   g_yh);
    cudaGetSymbolAddress((void**)&yl,   g_yl);
    cudaGetSymbolAddress((void**)&gh,   g_gh);
    cudaGetSymbolAddress((void**)&gl,   g_gl);
    cudaGetSymbolAddress((void**)&wqkvTh, g_wqkvT_h);
    cudaGetSymbolAddress((void**)&wqkvTl, g_wqkvT_l);
    cudaGetSymbolAddress((void**)&woTh,   g_woT_h);
    cudaGetSymbolAddress((void**)&woTl,   g_woT_l);
    cudaGetSymbolAddress((void**)&wfcTh,  g_wfcT_h);
    cudaGetSymbolAddress((void**)&wfcTl,  g_wfcT_l);
    cudaGetSymbolAddress((void**)&wprTh,  g_wprT_h);
    cudaGetSymbolAddress((void**)&wprTl,  g_wprT_l);
    cudaGetSymbolAddress((void**)&wlmTh,  g_wlmT_h);
    cudaGetSymbolAddress((void**)&wlmTl,  g_wlmT_l);

    cudaFuncSetAttribute(gemm_mma<0>, cudaFuncAttributeMaxDynamicSharedMemorySize, GSMEM);
    cudaFuncSetAttribute(gemm_mma<1>, cudaFuncAttributeMaxDynamicSharedMemorySize, GSMEM);
    cudaFuncSetAttribute(gemm_mma<2>, cudaFuncAttributeMaxDynamicSharedMemorySize, GSMEM);
    cudaFuncSetAttribute(gemm_mma<3>, cudaFuncAttributeMaxDynamicSharedMemorySize, GSMEM);

    // ---- weight prep: transpose + bf16 hi/lo split ----
    dim3 tb(32, 8);
    for (int l = 0; l < LAYERS; l++) {
        wsplit_kernel<<<dim3(3 * CDIM / 32, CDIM / 32), tb>>>(
            wqkv + (size_t)l * CDIM * 3 * CDIM,
            wqkvTh + (size_t)l * 3 * CDIM * CDIM, wqkvTl + (size_t)l * 3 * CDIM * CDIM,
            CDIM, 3 * CDIM);
        wsplit_kernel<<<dim3(CDIM / 32, CDIM / 32), tb>>>(
            wo + (size_t)l * CDIM * CDIM,
            woTh + (size_t)l * CDIM * CDIM, woTl + (size_t)l * CDIM * CDIM,
            CDIM, CDIM);
        wsplit_kernel<<<dim3(FFDIM / 32, CDIM / 32), tb>>>(
            wfc + (size_t)l * CDIM * FFDIM,
            wfcTh + (size_t)l * FFDIM * CDIM, wfcTl + (size_t)l * FFDIM * CDIM,
            CDIM, FFDIM);
        wsplit_kernel<<<dim3(CDIM / 32, FFDIM / 32), tb>>>(
            wpr + (size_t)l * FFDIM * CDIM,
            wprTh + (size_t)l * CDIM * FFDIM, wprTl + (size_t)l * CDIM * FFDIM,
            FFDIM, CDIM);
    }
    wsplit_kernel<<<dim3(VDIM / 32, CDIM / 32), tb>>>(wlm, wlmTh, wlmTl, CDIM, VDIM);

    embed_kernel<<<(NTOK * CDIM + 255) / 256, 256>>>(idx, tok, pos, x);

    dim3 gB(256);
    dim3 grid_qkv(3 * CDIM / GBN, NTOK / GBM);   // 6 x 256
    dim3 grid_prj(CDIM / GBN,     NTOK / GBM);   // 2 x 256
    dim3 grid_fc (FFDIM / GBN,    NTOK / GBM);   // 8 x 256
    dim3 grid_lm (VDIM / GBN,     NTOK / GBM);   // 1 x 256
    dim3 grid_att(TSEQ / QT, BATCH * HEADS);

    for (int l = 0; l < LAYERS; l++) {
        ln_kernel<<<NTOK, 256>>>(x, ln1g + l * CDIM, ln1b + l * CDIM, hh, hl);
        gemm_mma<1><<<grid_qkv, gB, GSMEM>>>(
            hh, hl,
            wqkvTh + (size_t)l * 3 * CDIM * CDIM, wqkvTl + (size_t)l * 3 * CDIM * CDIM,
            bqkv + (size_t)l * 3 * CDIM, nullptr, qkvb, nullptr, nullptr,
            CDIM, 3 * CDIM);
        attn_kernel<<<grid_att, QT>>>(qkvb, yh, yl);
        gemm_mma<2><<<grid_prj, gB, GSMEM>>>(
            yh, yl,
            woTh + (size_t)l * CDIM * CDIM, woTl + (size_t)l * CDIM * CDIM,
            bo + (size_t)l * CDIM, x, x, nullptr, nullptr,
            CDIM, CDIM);
        ln_kernel<<<NTOK, 256>>>(x, ln2g + l * CDIM, ln2b + l * CDIM, hh, hl);
        gemm_mma<3><<<grid_fc, gB, GSMEM>>>(
            hh, hl,
            wfcTh + (size_t)l * FFDIM * CDIM, wfcTl + (size_t)l * FFDIM * CDIM,
            bfc + (size_t)l * FFDIM, nullptr, nullptr, gh, gl,
            CDIM, FFDIM);
        gemm_mma<2><<<grid_prj, gB, GSMEM>>>(
            gh, gl,
            wprTh + (size_t)l * CDIM * FFDIM, wprTl + (size_t)l * CDIM * FFDIM,
            bpr + (size_t)l * CDIM, x, x, nullptr, nullptr,
            FFDIM, CDIM);
    }

    ln_kernel<<<NTOK, 256>>>(x, lnfg, lnfb, hh, hl);
    gemm_mma<0><<<grid_lm, gB, GSMEM>>>(
        hh, hl, wlmTh, wlmTl,
        nullptr, nullptr, out, nullptr, nullptr,
        CDIM, VDIM);
}

// round 4
// speedup vs baseline: 1.5358x; 1.0698x over previous
#include <cuda_runtime.h>
#include <cuda_bf16.h>
#include <cstdint>

// ---------------- problem constants (gpt-small) ----------------
#define LAYERS 8
#define HEADS  8
#define CDIM   256
#define VDIM   128
#define TSEQ   1024
#define BATCH  32
#define DHEAD  32
#define FFDIM  1024
#define NTOK   (BATCH * TSEQ)        // 32768

// ---------------- scratch (static device allocations) ----------------
__device__ float g_x  [(size_t)NTOK * CDIM];          // residual stream (fp32)
__device__ float g_qkv[(size_t)NTOK * 3 * CDIM];      // qkv (fp32) for attention
__device__ __nv_bfloat16 g_hh[(size_t)NTOK * CDIM];   // LN out hi
__device__ __nv_bfloat16 g_hl[(size_t)NTOK * CDIM];   // LN out lo
__device__ __nv_bfloat16 g_yh[(size_t)NTOK * CDIM];   // attn out hi
__device__ __nv_bfloat16 g_yl[(size_t)NTOK * CDIM];   // attn out lo
__device__ __nv_bfloat16 g_gh[(size_t)NTOK * FFDIM];  // gelu out hi
__device__ __nv_bfloat16 g_gl[(size_t)NTOK * FFDIM];  // gelu out lo
// transposed/split weights [N,K] bf16 hi/lo
__device__ __nv_bfloat16 g_wqkvT_h[(size_t)LAYERS * 3 * CDIM * CDIM];
__device__ __nv_bfloat16 g_wqkvT_l[(size_t)LAYERS * 3 * CDIM * CDIM];
__device__ __nv_bfloat16 g_woT_h  [(size_t)LAYERS * CDIM * CDIM];
__device__ __nv_bfloat16 g_woT_l  [(size_t)LAYERS * CDIM * CDIM];
__device__ __nv_bfloat16 g_wfcT_h [(size_t)LAYERS * FFDIM * CDIM];
__device__ __nv_bfloat16 g_wfcT_l [(size_t)LAYERS * FFDIM * CDIM];
__device__ __nv_bfloat16 g_wprT_h [(size_t)LAYERS * CDIM * FFDIM];
__device__ __nv_bfloat16 g_wprT_l [(size_t)LAYERS * CDIM * FFDIM];
__device__ __nv_bfloat16 g_wlmT_h [(size_t)VDIM * CDIM];
__device__ __nv_bfloat16 g_wlmT_l [(size_t)VDIM * CDIM];

// ---------------- low-level helpers ----------------
__device__ __forceinline__ uint32_t smem_to_u32(const void* p) {
    uint32_t a;
    asm("{ .reg .u64 t; cvta.to.shared.u64 t, %1; cvt.u32.u64 %0, t; }" : "=r"(a) : "l"(p));
    return a;
}
__device__ __forceinline__ void cp16(uint32_t s, const void* g) {
    asm volatile("cp.async.ca.shared.global [%0], [%1], 16;" :: "r"(s), "l"(g) : "memory");
}
#define CP_COMMIT() asm volatile("cp.async.commit_group;" ::: "memory")
#define CP_WAIT1()  asm volatile("cp.async.wait_group 1;" ::: "memory")
#define CP_WAIT0()  asm volatile("cp.async.wait_group 0;" ::: "memory")

__device__ __forceinline__ void ldm4(uint32_t a, uint32_t& r0, uint32_t& r1,
                                     uint32_t& r2, uint32_t& r3) {
    asm volatile("ldmatrix.sync.aligned.m8n8.x4.shared.b16 {%0,%1,%2,%3}, [%4];"
        : "=r"(r0), "=r"(r1), "=r"(r2), "=r"(r3) : "r"(a));
}
__device__ __forceinline__ void mma16816(float* c, const uint32_t* a, const uint32_t* b) {
    asm volatile("mma.sync.aligned.m16n8k16.row.col.f32.bf16.bf16.f32 "
        "{%0,%1,%2,%3}, {%4,%5,%6,%7}, {%8,%9}, {%0,%1,%2,%3};"
        : "+f"(c[0]), "+f"(c[1]), "+f"(c[2]), "+f"(c[3])
        : "r"(a[0]), "r"(a[1]), "r"(a[2]), "r"(a[3]), "r"(b[0]), "r"(b[1]));
}

// packed f32x2 (B300: FFMA2 only reachable via PTX fma.rn.f32x2)
__device__ __forceinline__ uint64_t pack2(float lo, float hi) {
    uint64_t r; asm("mov.b64 %0, {%1, %2};" : "=l"(r) : "f"(lo), "f"(hi)); return r;
}
__device__ __forceinline__ void unpack2(uint64_t v, float& lo, float& hi) {
    asm("mov.b64 {%0, %1}, %2;" : "=f"(lo), "=f"(hi) : "l"(v));
}
__device__ __forceinline__ uint64_t fma2(uint64_t a, uint64_t b, uint64_t c) {
    uint64_t d; asm("fma.rn.f32x2 %0, %1, %2, %3;" : "=l"(d) : "l"(a), "l"(b), "l"(c)); return d;
}
__device__ __forceinline__ uint64_t add2(uint64_t a, uint64_t b) {
    uint64_t d; asm("add.rn.f32x2 %0, %1, %2;" : "=l"(d) : "l"(a), "l"(b)); return d;
}
__device__ __forceinline__ uint64_t mul2(uint64_t a, uint64_t b) {
    uint64_t d; asm("mul.rn.f32x2 %0, %1, %2;" : "=l"(d) : "l"(a), "l"(b)); return d;
}

// ---------------- math helpers ----------------
__device__ __forceinline__ float warp_sum(float v) {
    #pragma unroll
    for (int o = 16; o; o >>= 1) v += __shfl_xor_sync(0xFFFFFFFFu, v, o);
    return v;
}
// HW exp2 via MUFU (error ~2^-22; MUFU pipe idle in these kernels)
__device__ __forceinline__ float ex2f(float x) {
    float y; asm("ex2.approx.f32 %0, %1;" : "=f"(y) : "f"(x)); return y;
}
__device__ __forceinline__ float tanh_fast(float x) {
    float y; asm("tanh.approx.f32 %0, %1;" : "=f"(y) : "f"(x)); return y;
}
__device__ __forceinline__ float gelu_f(float x) {
    float x3 = x * x * x;
    float u  = 0.7978845608028654f * fmaf(0.044715f, x3, x);
    return 0.5f * x * (1.0f + tanh_fast(u));
}
__device__ __forceinline__ void bf16split(float v, __nv_bfloat16& h, __nv_bfloat16& l) {
    h = __float2bfloat16(v);
    l = __float2bfloat16(v - __bfloat162float(h));
}

// ---------------- batched weight transpose + bf16 hi/lo split ----------------
// 5 segment types; flat blockIdx.x decodes (type, layer, tile).
// blocks/layer: qkv 24x8=192, wo 8x8=64, wfc 32x8=256, wpr 8x32=256, wlm 4x8=32
#define WS_T0_END 1536        // qkv: 8*192
#define WS_T1_END 2048        // wo:  8*64
#define WS_T2_END 4096        // wfc: 8*256
#define WS_T3_END 6144        // wpr: 8*256
#define WS_TOTAL  6176        // + wlm 32

__global__ void wsplit_all(const float* __restrict__ wqkv, const float* __restrict__ wo,
                           const float* __restrict__ wfc,  const float* __restrict__ wpr,
                           const float* __restrict__ wlm,
                           __nv_bfloat16* qkvh, __nv_bfloat16* qkvl,
                           __nv_bfloat16* woh,  __nv_bfloat16* wol,
                           __nv_bfloat16* fch,  __nv_bfloat16* fcl,
                           __nv_bfloat16* prh,  __nv_bfloat16* prl,
                           __nv_bfloat16* lmh,  __nv_bfloat16* lml) {
    int bid = blockIdx.x;
    const float* W; __nv_bfloat16 *Th, *Tl;
    int K, N, bxc, tile;
    if (bid < WS_T0_END) {
        int layer = bid / 192; tile = bid % 192;
        K = CDIM; N = 3 * CDIM; bxc = 24;
        W  = wqkv + (size_t)layer * K * N;
        Th = qkvh + (size_t)layer * N * K; Tl = qkvl + (size_t)layer * N * K;
    } else if (bid < WS_T1_END) {
        int r = bid - WS_T0_END; int layer = r / 64; tile = r % 64;
        K = CDIM; N = CDIM; bxc = 8;
        W  = wo  + (size_t)layer * K * N;
        Th = woh + (size_t)layer * N * K; Tl = wol + (size_t)layer * N * K;
    } else if (bid < WS_T2_END) {
        int r = bid - WS_T1_END; int layer = r / 256; tile = r % 256;
        K = CDIM; N = FFDIM; bxc = 32;
        W  = wfc + (size_t)layer * K * N;
        Th = fch + (size_t)layer * N * K; Tl = fcl + (size_t)layer * N * K;
    } else if (bid < WS_T3_END) {
        int r = bid - WS_T2_END; int layer = r / 256; tile = r % 256;
        K = FFDIM; N = CDIM; bxc = 8;
        W  = wpr + (size_t)layer * K * N;
        Th = prh + (size_t)layer * N * K; Tl = prl + (size_t)layer * N * K;
    } else {
        tile = bid - WS_T3_END;
        K = CDIM; N = VDIM; bxc = 4;
        W = wlm; Th = lmh; Tl = lml;
    }
    int nx = (tile % bxc) * 32, kx = (tile / bxc) * 32;

    __shared__ float t[32][33];
    #pragma unroll
    for (int i = 0; i < 4; i++) {
        int k = kx + threadIdx.y + i * 8;
        t[threadIdx.y + i * 8][threadIdx.x] = W[(size_t)k * N + nx + threadIdx.x];
    }
    __syncthreads();
    #pragma unroll
    for (int i = 0; i < 4; i++) {
        int n = nx + threadIdx.y + i * 8;
        int k = kx + threadIdx.x;
        float v = t[threadIdx.x][threadIdx.y + i * 8];
        __nv_bfloat16 h, l; bf16split(v, h, l);
        Th[(size_t)n * K + k] = h;
        Tl[(size_t)n * K + k] = l;
    }
}

// ---------------- embedding ----------------
__global__ void embed_kernel(const int* __restrict__ idx,
                             const float* __restrict__ tok,
                             const float* __restrict__ pos,
                             float* __restrict__ x) {
    int i = blockIdx.x * blockDim.x + threadIdx.x;
    if (i >= NTOK * CDIM) return;
    int row = i >> 8;
    int c   = i & (CDIM - 1);
    int t   = row & (TSEQ - 1);
    x[i] = tok[(size_t)idx[row] * CDIM + c] + pos[(size_t)t * CDIM + c];
}

// ---------------- layernorm -> bf16 hi/lo pair ----------------
__global__ void ln_kernel(const float* __restrict__ x,
                          const float* __restrict__ g,
                          const float* __restrict__ b,
                          __nv_bfloat16* __restrict__ oh,
                          __nv_bfloat16* __restrict__ ol) {
    int row = blockIdx.x;
    int c   = threadIdx.x;
    float v = x[(size_t)row * CDIM + c];
    float s1 = warp_sum(v);
    float s2 = warp_sum(v * v);
    __shared__ float sh1[8], sh2[8];
    int w = c >> 5, lane = c & 31;
    if (lane == 0) { sh1[w] = s1; sh2[w] = s2; }
    __syncthreads();
    float t1 = 0.f, t2 = 0.f;
    #pragma unroll
    for (int i = 0; i < 8; i++) { t1 += sh1[i]; t2 += sh2[i]; }
    float mean = t1 * (1.0f / CDIM);
    float var  = t2 * (1.0f / CDIM) - mean * mean;
    float rstd = rsqrtf(var + 1e-5f);
    float o = (v - mean) * rstd * g[c] + b[c];
    __nv_bfloat16 h, l; bf16split(o, h, l);
    oh[(size_t)row * CDIM + c] = h;
    ol[(size_t)row * CDIM + c] = l;
}

// ---------------- mma.sync bf16x3 GEMM ----------------
// D[M,N] = A[M,K] @ Bt[N,K]^T.  A/B are bf16 hi/lo pairs; fp32 accumulators.
// Block 128x128, BK=32, 256 threads = 8 warps (warp tile 32x64), cp.async 2-stage.
// MODE 0: plain fp32   1: +bias fp32   2: +bias +residual fp32
// MODE 3: +bias, GELU -> bf16 hi/lo outputs
#define GBM 128
#define GBN 128
#define GBK 32
#define ROWB 80                         // smem row pitch: 64B data + 16B pad
#define TILE_B (128 * ROWB)             // 10240 bytes per tile
#define STAGE_B (4 * TILE_B)            // Ah, Al, Bh, Bl
#define GSMEM (2 * STAGE_B)             // 81920 bytes

template<int MODE>
__global__ __launch_bounds__(256, 1)
void gemm_mma(const __nv_bfloat16* __restrict__ Ah, const __nv_bfloat16* __restrict__ Al,
              const __nv_bfloat16* __restrict__ Bh, const __nv_bfloat16* __restrict__ Bl,
              const float* __restrict__ bias, const float* __restrict__ res,
              float* __restrict__ outF,
              __nv_bfloat16* __restrict__ outH, __nv_bfloat16* __restrict__ outL,
              int K, int No)
{
    extern __shared__ char smem[];
    uint32_t sU = smem_to_u32(smem);
    int tid  = threadIdx.x;
    int wid  = tid >> 5, lane = tid & 31;
    int warp_m = wid & 3, warp_n = wid >> 2;
    int m0 = blockIdx.y * GBM, n0 = blockIdx.x * GBN;

    float C[2][8][4];
    #pragma unroll
    for (int mt = 0; mt < 2; mt++)
        #pragma unroll
        for (int nt = 0; nt < 8; nt++)
            #pragma unroll
            for (int k = 0; k < 4; k++) C[mt][nt][k] = 0.f;

    // per-thread load coords: 512 16B-chunks per tile, 2 per thread
    int lr0 = tid >> 2,  lc0 = (tid & 3);
    int lr1 = (tid + 256) >> 2, lc1 = ((tid + 256) & 3);

    int nch = K >> 5;
    // ---- stage loader ----
    auto load_stage = [&](int ch, int buf) {
        int k0 = ch * GBK;
        uint32_t sb = sU + buf * STAGE_B;
        {
            uint32_t so = lr0 * ROWB + lc0 * 16;
            cp16(sb + so,              Ah + (size_t)(m0 + lr0) * K + k0 + lc0 * 8);
            cp16(sb + TILE_B + so,     Al + (size_t)(m0 + lr0) * K + k0 + lc0 * 8);
            cp16(sb + 2 * TILE_B + so, Bh + (size_t)(n0 + lr0) * K + k0 + lc0 * 8);
            cp16(sb + 3 * TILE_B + so, Bl + (size_t)(n0 + lr0) * K + k0 + lc0 * 8);
        }
        {
            uint32_t so = lr1 * ROWB + lc1 * 16;
            cp16(sb + so,              Ah + (size_t)(m0 + lr1) * K + k0 + lc1 * 8);
            cp16(sb + TILE_B + so,     Al + (size_t)(m0 + lr1) * K + k0 + lc1 * 8);
            cp16(sb + 2 * TILE_B + so, Bh + (size_t)(n0 + lr1) * K + k0 + lc1 * 8);
            cp16(sb + 3 * TILE_B + so, Bl + (size_t)(n0 + lr1) * K + k0 + lc1 * 8);
        }
    };

    load_stage(0, 0);
    CP_COMMIT();

    int rin = lane & 7;
    int amat = lane >> 3;               // A: mat index 0..3
    int bnt  = (lane >> 4) & 1;         // B: n-subtile within group
    int bkh  = (lane >> 3) & 1;         // B: k-half

    for (int ch = 0; ch < nch; ch++) {
        int buf = ch & 1;
        if (ch + 1 < nch) load_stage(ch + 1, buf ^ 1);
        CP_COMMIT();
        CP_WAIT1();
        __syncthreads();

        uint32_t sA  = sU + buf * STAGE_B;
        uint32_t sAl = sA + TILE_B;
        uint32_t sBh = sA + 2 * TILE_B;
        uint32_t sBl = sA + 3 * TILE_B;

        #pragma unroll
        for (int s = 0; s < 2; s++) {
            uint32_t ah[2][4], al[2][4], bh[8][2], bl[8][2];
            #pragma unroll
            for (int mt = 0; mt < 2; mt++) {
                int row = warp_m * 32 + mt * 16 + (amat & 1) * 8 + rin;
                uint32_t off = row * ROWB + (amat >> 1) * 16 + s * 32;
                ldm4(sA  + off, ah[mt][0], ah[mt][1], ah[mt][2], ah[mt][3]);
                ldm4(sAl + off, al[mt][0], al[mt][1], al[mt][2], al[mt][3]);
            }
            #pragma unroll
            for (int ng = 0; ng < 4; ng++) {
                int row = warp_n * 64 + ng * 16 + bnt * 8 + rin;
                uint32_t off = row * ROWB + bkh * 16 + s * 32;
                ldm4(sBh + off, bh[2*ng][0], bh[2*ng][1], bh[2*ng+1][0], bh[2*ng+1][1]);
                ldm4(sBl + off, bl[2*ng][0], bl[2*ng][1], bl[2*ng+1][0], bl[2*ng+1][1]);
            }
            #pragma unroll
            for (int mt = 0; mt < 2; mt++)
                #pragma unroll
                for (int nt = 0; nt < 8; nt++) {
                    mma16816(C[mt][nt], ah[mt], bh[nt]);
                    mma16816(C[mt][nt], ah[mt], bl[nt]);
                    mma16816(C[mt][nt], al[mt], bh[nt]);
                }
        }
        __syncthreads();
    }
    CP_WAIT0();

    // ---- epilogue ----
    int rbase = m0 + warp_m * 32;
    int cbase = n0 + warp_n * 64;
    #pragma unroll
    for (int mt = 0; mt < 2; mt++) {
        #pragma unroll
        for (int nt = 0; nt < 8; nt++) {
            int row = rbase + mt * 16 + (lane >> 2);
            int col = cbase + nt * 8 + (lane & 3) * 2;
            const float* c = C[mt][nt];
            float2 b2 = make_float2(0.f, 0.f);
            if (MODE >= 1) b2 = *(const float2*)(bias + col);
            if (MODE == 3) {
                float g0 = gelu_f(c[0] + b2.x), g1 = gelu_f(c[1] + b2.y);
                float g2 = gelu_f(c[2] + b2.x), g3 = gelu_f(c[3] + b2.y);
                __nv_bfloat16 h0, l0, h1, l1;
                bf16split(g0, h0, l0); bf16split(g1, h1, l1);
                *(__nv_bfloat162*)(outH + (size_t)row * No + col) = __nv_bfloat162(h0, h1);
                *(__nv_bfloat162*)(outL + (size_t)row * No + col) = __nv_bfloat162(l0, l1);
                bf16split(g2, h0, l0); bf16split(g3, h1, l1);
                *(__nv_bfloat162*)(outH + (size_t)(row + 8) * No + col) = __nv_bfloat162(h0, h1);
                *(__nv_bfloat162*)(outL + (size_t)(row + 8) * No + col) = __nv_bfloat162(l0, l1);
            } else {
                float2 v0 = make_float2(c[0] + b2.x, c[1] + b2.y);
                float2 v1 = make_float2(c[2] + b2.x, c[3] + b2.y);
                if (MODE == 2) {
                    float2 r0 = *(const float2*)(res + (size_t)row * No + col);
                    float2 r1 = *(const float2*)(res + (size_t)(row + 8) * No + col);
                    v0.x += r0.x; v0.y += r0.y; v1.x += r1.x; v1.y += r1.y;
                }
                *(float2*)(outF + (size_t)row * No + col) = v0;
                *(float2*)(outF + (size_t)(row + 8) * No + col) = v1;
            }
        }
    }
}

// ---------------- causal attention, packed f32x2 math ----------------
#define QT 128
#define KT 128
#define LOG2E 1.4426950408889634f

__global__ __launch_bounds__(QT) void attn_kernel(const float* __restrict__ qkv,
                                                  __nv_bfloat16* __restrict__ yh,
                                                  __nv_bfloat16* __restrict__ yl) {
    __shared__ uint64_t Ks2[KT][16];
    __shared__ uint64_t Vs2[KT][16];
    int bh_ = blockIdx.y;
    int b = bh_ >> 3, h = bh_ & 7;
    int tid = threadIdx.x;
    int t = blockIdx.x * QT + tid;

    const float qscale = 0.17677669529663687f * LOG2E;
    const float* qp = qkv + ((size_t)(b * TSEQ + t) * (3 * CDIM)) + h * DHEAD;
    uint64_t q2[16];
    #pragma unroll
    for (int i = 0; i < 16; i++)
        q2[i] = pack2(qp[2 * i] * qscale, qp[2 * i + 1] * qscale);

    uint64_t o2[16];
    #pragma unroll
    for (int i = 0; i < 16; i++) o2[i] = 0ull;
    float m = -1e30f, l = 0.f;

    int ntiles = blockIdx.x + 1;
    for (int kb = 0; kb < ntiles; kb++) {
        int j0 = kb * KT;
        __syncthreads();
        #pragma unroll
        for (int i = 0; i < 8; i++) {
            int idx = tid + i * QT;             // 0..1023
            int r = idx >> 3;
            int c4 = (idx & 7) * 4;             // float index within row
            const float* kp = qkv + ((size_t)(b * TSEQ + j0 + r) * (3 * CDIM))
                              + CDIM + h * DHEAD + c4;
            *(float4*)((char*)Ks2[r] + c4 * 4) = *(const float4*)kp;
            *(float4*)((char*)Vs2[r] + c4 * 4) = *(const float4*)(kp + CDIM);
        }
        __syncthreads();

        int jmax = min(KT, t - j0 + 1);
        for (int jj = 0; jj < jmax; jj++) {
            const uint64_t* kr = Ks2[jj];
            uint64_t a0 = 0, a1 = 0, a2 = 0, a3 = 0;
            #pragma unroll
            for (int i = 0; i < 16; i += 4) {
                a0 = fma2(q2[i],     kr[i],     a0);
                a1 = fma2(q2[i + 1], kr[i + 1], a1);
                a2 = fma2(q2[i + 2], kr[i + 2], a2);
                a3 = fma2(q2[i + 3], kr[i + 3], a3);
            }
            a0 = add2(a0, a1); a2 = add2(a2, a3); a0 = add2(a0, a2);
            float slo, shi; unpack2(a0, slo, shi);
            float s = slo + shi;

            if (s > m) {
                float corr = ex2f(m - s);
                l *= corr;
                uint64_t c2p = pack2(corr, corr);
                #pragma unroll
                for (int i = 0; i < 16; i++) o2[i] = mul2(c2p, o2[i]);
                m = s;
            }
            float p = ex2f(s - m);
            l += p;
            uint64_t p2 = pack2(p, p);
            const uint64_t* vr = Vs2[jj];
            #pragma unroll
            for (int i = 0; i < 16; i++) o2[i] = fma2(p2, vr[i], o2[i]);
        }
    }

    float inv = 1.0f / l;
    size_t base = (size_t)(b * TSEQ + t) * CDIM + h * DHEAD;
    #pragma unroll
    for (int i = 0; i < 16; i++) {
        float lo, hi; unpack2(o2[i], lo, hi);
        __nv_bfloat16 h0, l0, h1, l1;
        bf16split(lo * inv, h0, l0);
        bf16split(hi * inv, h1, l1);
        *(__nv_bfloat162*)(yh + base + 2 * i) = __nv_bfloat162(h0, h1);
        *(__nv_bfloat162*)(yl + base + 2 * i) = __nv_bfloat162(l0, l1);
    }
}

// ---------------- host orchestration (graph-capturable) ----------------
extern "C" void kernel_launch(void* const* d_in, const int* in_sizes, int n_in,
                              void* d_out, int out_size) {
    (void)in_sizes; (void)n_in; (void)out_size;
    const int*   idx   = (const int*)  d_in[0];
    const float* tok   = (const float*)d_in[1];
    const float* pos   = (const float*)d_in[2];
    const float* ln1g  = (const float*)d_in[3];
    const float* ln1b  = (const float*)d_in[4];
    const float* wqkv  = (const float*)d_in[5];
    const float* bqkv  = (const float*)d_in[6];
    const float* wo    = (const float*)d_in[7];
    const float* bo    = (const float*)d_in[8];
    const float* ln2g  = (const float*)d_in[9];
    const float* ln2b  = (const float*)d_in[10];
    const float* wfc   = (const float*)d_in[11];
    const float* bfc   = (const float*)d_in[12];
    const float* wpr   = (const float*)d_in[13];
    const float* bpr   = (const float*)d_in[14];
    const float* lnfg  = (const float*)d_in[15];
    const float* lnfb  = (const float*)d_in[16];
    const float* wlm   = (const float*)d_in[17];
    float* out = (float*)d_out;

    float *x, *qkvb;
    __nv_bfloat16 *hh, *hl, *yh, *yl, *gh, *gl;
    __nv_bfloat16 *wqkvTh, *wqkvTl, *woTh, *woTl, *wfcTh, *wfcTl, *wprTh, *wprTl, *wlmTh, *wlmTl;
    cudaGetSymbolAddress((void**)&x,    g_x);
    cudaGetSymbolAddress((void**)&qkvb, g_qkv);
    cudaGetSymbolAddress((void**)&hh,   g_hh);
    cudaGetSymbolAddress((void**)&hl,   g_hl);
    cudaGetSymbolAddress((void**)&yh,   g_yh);
    cudaGetSymbolAddress((void**)&yl,   g_yl);
    cudaGetSymbolAddress((void**)&gh,   g_gh);
    cudaGetSymbolAddress((void**)&gl,   g_gl);
    cudaGetSymbolAddress((void**)&wqkvTh, g_wqkvT_h);
    cudaGetSymbolAddress((void**)&wqkvTl, g_wqkvT_l);
    cudaGetSymbolAddress((void**)&woTh,   g_woT_h);
    cudaGetSymbolAddress((void**)&woTl,   g_woT_l);
    cudaGetSymbolAddress((void**)&wfcTh,  g_wfcT_h);
    cudaGetSymbolAddress((void**)&wfcTl,  g_wfcT_l);
    cudaGetSymbolAddress((void**)&wprTh,  g_wprT_h);
    cudaGetSymbolAddress((void**)&wprTl,  g_wprT_l);
    cudaGetSymbolAddress((void**)&wlmTh,  g_wlmT_h);
    cudaGetSymbolAddress((void**)&wlmTl,  g_wlmT_l);

    cudaFuncSetAttribute(gemm_mma<0>, cudaFuncAttributeMaxDynamicSharedMemorySize, GSMEM);
    cudaFuncSetAttribute(gemm_mma<1>, cudaFuncAttributeMaxDynamicSharedMemorySize, GSMEM);
    cudaFuncSetAttribute(gemm_mma<2>, cudaFuncAttributeMaxDynamicSharedMemorySize, GSMEM);
    cudaFuncSetAttribute(gemm_mma<3>, cudaFuncAttributeMaxDynamicSharedMemorySize, GSMEM);

    // ---- weight prep: single batched launch ----
    wsplit_all<<<WS_TOTAL, dim3(32, 8)>>>(
        wqkv, wo, wfc, wpr, wlm,
        wqkvTh, wqkvTl, woTh, woTl, wfcTh, wfcTl, wprTh, wprTl, wlmTh, wlmTl);

    embed_kernel<<<(NTOK * CDIM + 255) / 256, 256>>>(idx, tok, pos, x);

    dim3 gB(256);
    dim3 grid_qkv(3 * CDIM / GBN, NTOK / GBM);   // 6 x 256
    dim3 grid_prj(CDIM / GBN,     NTOK / GBM);   // 2 x 256
    dim3 grid_fc (FFDIM / GBN,    NTOK / GBM);   // 8 x 256
    dim3 grid_lm (VDIM / GBN,     NTOK / GBM);   // 1 x 256
    dim3 grid_att(TSEQ / QT, BATCH * HEADS);

    for (int l = 0; l < LAYERS; l++) {
        ln_kernel<<<NTOK, 256>>>(x, ln1g + l * CDIM, ln1b + l * CDIM, hh, hl);
        gemm_mma<1><<<grid_qkv, gB, GSMEM>>>(
            hh, hl,
            wqkvTh + (size_t)l * 3 * CDIM * CDIM, wqkvTl + (size_t)l * 3 * CDIM * CDIM,
            bqkv + (size_t)l * 3 * CDIM, nullptr, qkvb, nullptr, nullptr,
            CDIM, 3 * CDIM);
        attn_kernel<<<grid_att, QT>>>(qkvb, yh, yl);
        gemm_mma<2><<<grid_prj, gB, GSMEM>>>(
            yh, yl,
            woTh + (size_t)l * CDIM * CDIM, woTl + (size_t)l * CDIM * CDIM,
            bo + (size_t)l * CDIM, x, x, nullptr, nullptr,
            CDIM, CDIM);
        ln_kernel<<<NTOK, 256>>>(x, ln2g + l * CDIM, ln2b + l * CDIM, hh, hl);
        gemm_mma<3><<<grid_fc, gB, GSMEM>>>(
            hh, hl,
            wfcTh + (size_t)l * FFDIM * CDIM, wfcTl + (size_t)l * FFDIM * CDIM,
            bfc + (size_t)l * FFDIM, nullptr, nullptr, gh, gl,
            CDIM, FFDIM);
        gemm_mma<2><<<grid_prj, gB, GSMEM>>>(
            gh, gl,
            wprTh + (size_t)l * CDIM * FFDIM, wprTl + (size_t)l * CDIM * FFDIM,
            bpr + (size_t)l * CDIM, x, x, nullptr, nullptr,
            FFDIM, CDIM);
    }

    ln_kernel<<<NTOK, 256>>>(x, lnfg, lnfb, hh, hl);
    gemm_mma<0><<<grid_lm, gB, GSMEM>>>(
        hh, hl, wlmTh, wlmTl,
        nullptr, nullptr, out, nullptr, nullptr,
        CDIM, VDIM);
}

// round 5
// speedup vs baseline: 2.7294x; 1.7771x over previous
#include <cuda_runtime.h>
#include <cuda_bf16.h>
#include <cstdint>

// ---------------- problem constants (gpt-small) ----------------
#define LAYERS 8
#define HEADS  8
#define CDIM   256
#define VDIM   128
#define TSEQ   1024
#define BATCH  32
#define DHEAD  32
#define FFDIM  1024
#define NTOK   (BATCH * TSEQ)        // 32768

// ---------------- scratch (static device allocations) ----------------
__device__ float g_x  [(size_t)NTOK * CDIM];            // residual stream (fp32)
__device__ __nv_bfloat16 g_qkvh[(size_t)NTOK * 3 * CDIM];
__device__ __nv_bfloat16 g_qkvl[(size_t)NTOK * 3 * CDIM];
__device__ __nv_bfloat16 g_hh[(size_t)NTOK * CDIM];
__device__ __nv_bfloat16 g_hl[(size_t)NTOK * CDIM];
__device__ __nv_bfloat16 g_yh[(size_t)NTOK * CDIM];
__device__ __nv_bfloat16 g_yl[(size_t)NTOK * CDIM];
__device__ __nv_bfloat16 g_gh[(size_t)NTOK * FFDIM];
__device__ __nv_bfloat16 g_gl[(size_t)NTOK * FFDIM];
// transposed/split weights [N,K] bf16 hi/lo
__device__ __nv_bfloat16 g_wqkvT_h[(size_t)LAYERS * 3 * CDIM * CDIM];
__device__ __nv_bfloat16 g_wqkvT_l[(size_t)LAYERS * 3 * CDIM * CDIM];
__device__ __nv_bfloat16 g_woT_h  [(size_t)LAYERS * CDIM * CDIM];
__device__ __nv_bfloat16 g_woT_l  [(size_t)LAYERS * CDIM * CDIM];
__device__ __nv_bfloat16 g_wfcT_h [(size_t)LAYERS * FFDIM * CDIM];
__device__ __nv_bfloat16 g_wfcT_l [(size_t)LAYERS * FFDIM * CDIM];
__device__ __nv_bfloat16 g_wprT_h [(size_t)LAYERS * CDIM * FFDIM];
__device__ __nv_bfloat16 g_wprT_l [(size_t)LAYERS * CDIM * FFDIM];
__device__ __nv_bfloat16 g_wlmT_h [(size_t)VDIM * CDIM];
__device__ __nv_bfloat16 g_wlmT_l [(size_t)VDIM * CDIM];

// ---------------- low-level helpers ----------------
__device__ __forceinline__ uint32_t smem_to_u32(const void* p) {
    uint32_t a;
    asm("{ .reg .u64 t; cvta.to.shared.u64 t, %1; cvt.u32.u64 %0, t; }" : "=r"(a) : "l"(p));
    return a;
}
__device__ __forceinline__ void cp16(uint32_t s, const void* g) {
    asm volatile("cp.async.ca.shared.global [%0], [%1], 16;" :: "r"(s), "l"(g) : "memory");
}
#define CP_COMMIT() asm volatile("cp.async.commit_group;" ::: "memory")
#define CP_WAIT1()  asm volatile("cp.async.wait_group 1;" ::: "memory")
#define CP_WAIT0()  asm volatile("cp.async.wait_group 0;" ::: "memory")

__device__ __forceinline__ void ldm4(uint32_t a, uint32_t& r0, uint32_t& r1,
                                     uint32_t& r2, uint32_t& r3) {
    asm volatile("ldmatrix.sync.aligned.m8n8.x4.shared.b16 {%0,%1,%2,%3}, [%4];"
        : "=r"(r0), "=r"(r1), "=r"(r2), "=r"(r3) : "r"(a));
}
__device__ __forceinline__ void ldm4t(uint32_t a, uint32_t& r0, uint32_t& r1,
                                      uint32_t& r2, uint32_t& r3) {
    asm volatile("ldmatrix.sync.aligned.m8n8.x4.trans.shared.b16 {%0,%1,%2,%3}, [%4];"
        : "=r"(r0), "=r"(r1), "=r"(r2), "=r"(r3) : "r"(a));
}
__device__ __forceinline__ void mma16816(float* c, const uint32_t* a, const uint32_t* b) {
    asm volatile("mma.sync.aligned.m16n8k16.row.col.f32.bf16.bf16.f32 "
        "{%0,%1,%2,%3}, {%4,%5,%6,%7}, {%8,%9}, {%0,%1,%2,%3};"
        : "+f"(c[0]), "+f"(c[1]), "+f"(c[2]), "+f"(c[3])
        : "r"(a[0]), "r"(a[1]), "r"(a[2]), "r"(a[3]), "r"(b[0]), "r"(b[1]));
}

// ---------------- math helpers ----------------
__device__ __forceinline__ float warp_sum(float v) {
    #pragma unroll
    for (int o = 16; o; o >>= 1) v += __shfl_xor_sync(0xFFFFFFFFu, v, o);
    return v;
}
__device__ __forceinline__ float ex2f(float x) {
    float y; asm("ex2.approx.f32 %0, %1;" : "=f"(y) : "f"(x)); return y;
}
__device__ __forceinline__ float tanh_fast(float x) {
    float y; asm("tanh.approx.f32 %0, %1;" : "=f"(y) : "f"(x)); return y;
}
__device__ __forceinline__ float gelu_f(float x) {
    float x3 = x * x * x;
    float u  = 0.7978845608028654f * fmaf(0.044715f, x3, x);
    return 0.5f * x * (1.0f + tanh_fast(u));
}
__device__ __forceinline__ void bf16split(float v, __nv_bfloat16& h, __nv_bfloat16& l) {
    h = __float2bfloat16(v);
    l = __float2bfloat16(v - __bfloat162float(h));
}
// pack two floats as bf16x2 hi + bf16x2 lo-residual
__device__ __forceinline__ void bfpack2(float a, float b, uint32_t& hi, uint32_t& lo) {
    __nv_bfloat16 ha, la, hb, lb;
    bf16split(a, ha, la);
    bf16split(b, hb, lb);
    __nv_bfloat162 H(ha, hb), L(la, lb);
    hi = *(uint32_t*)&H;
    lo = *(uint32_t*)&L;
}

// ---------------- batched weight transpose + bf16 hi/lo split ----------------
#define WS_T0_END 1536
#define WS_T1_END 2048
#define WS_T2_END 4096
#define WS_T3_END 6144
#define WS_TOTAL  6176

__global__ void wsplit_all(const float* __restrict__ wqkv, const float* __restrict__ wo,
                           const float* __restrict__ wfc,  const float* __restrict__ wpr,
                           const float* __restrict__ wlm,
                           __nv_bfloat16* qkvh, __nv_bfloat16* qkvl,
                           __nv_bfloat16* woh,  __nv_bfloat16* wol,
                           __nv_bfloat16* fch,  __nv_bfloat16* fcl,
                           __nv_bfloat16* prh,  __nv_bfloat16* prl,
                           __nv_bfloat16* lmh,  __nv_bfloat16* lml) {
    int bid = blockIdx.x;
    const float* W; __nv_bfloat16 *Th, *Tl;
    int K, N, bxc, tile;
    if (bid < WS_T0_END) {
        int layer = bid / 192; tile = bid % 192;
        K = CDIM; N = 3 * CDIM; bxc = 24;
        W  = wqkv + (size_t)layer * K * N;
        Th = qkvh + (size_t)layer * N * K; Tl = qkvl + (size_t)layer * N * K;
    } else if (bid < WS_T1_END) {
        int r = bid - WS_T0_END; int layer = r / 64; tile = r % 64;
        K = CDIM; N = CDIM; bxc = 8;
        W  = wo  + (size_t)layer * K * N;
        Th = woh + (size_t)layer * N * K; Tl = wol + (size_t)layer * N * K;
    } else if (bid < WS_T2_END) {
        int r = bid - WS_T1_END; int layer = r / 256; tile = r % 256;
        K = CDIM; N = FFDIM; bxc = 32;
        W  = wfc + (size_t)layer * K * N;
        Th = fch + (size_t)layer * N * K; Tl = fcl + (size_t)layer * N * K;
    } else if (bid < WS_T3_END) {
        int r = bid - WS_T2_END; int layer = r / 256; tile = r % 256;
        K = FFDIM; N = CDIM; bxc = 8;
        W  = wpr + (size_t)layer * K * N;
        Th = prh + (size_t)layer * N * K; Tl = prl + (size_t)layer * N * K;
    } else {
        tile = bid - WS_T3_END;
        K = CDIM; N = VDIM; bxc = 4;
        W = wlm; Th = lmh; Tl = lml;
    }
    int nx = (tile % bxc) * 32, kx = (tile / bxc) * 32;

    __shared__ float t[32][33];
    #pragma unroll
    for (int i = 0; i < 4; i++) {
        int k = kx + threadIdx.y + i * 8;
        t[threadIdx.y + i * 8][threadIdx.x] = W[(size_t)k * N + nx + threadIdx.x];
    }
    __syncthreads();
    #pragma unroll
    for (int i = 0; i < 4; i++) {
        int n = nx + threadIdx.y + i * 8;
        int k = kx + threadIdx.x;
        float v = t[threadIdx.x][threadIdx.y + i * 8];
        __nv_bfloat16 h, l; bf16split(v, h, l);
        Th[(size_t)n * K + k] = h;
        Tl[(size_t)n * K + k] = l;
    }
}

// ---------------- embedding ----------------
__global__ void embed_kernel(const int* __restrict__ idx,
                             const float* __restrict__ tok,
                             const float* __restrict__ pos,
                             float* __restrict__ x) {
    int i = blockIdx.x * blockDim.x + threadIdx.x;
    if (i >= NTOK * CDIM) return;
    int row = i >> 8;
    int c   = i & (CDIM - 1);
    int t   = row & (TSEQ - 1);
    x[i] = tok[(size_t)idx[row] * CDIM + c] + pos[(size_t)t * CDIM + c];
}

// ---------------- layernorm -> bf16 hi/lo pair ----------------
__global__ void ln_kernel(const float* __restrict__ x,
                          const float* __restrict__ g,
                          const float* __restrict__ b,
                          __nv_bfloat16* __restrict__ oh,
                          __nv_bfloat16* __restrict__ ol) {
    int row = blockIdx.x;
    int c   = threadIdx.x;
    float v = x[(size_t)row * CDIM + c];
    float s1 = warp_sum(v);
    float s2 = warp_sum(v * v);
    __shared__ float sh1[8], sh2[8];
    int w = c >> 5, lane = c & 31;
    if (lane == 0) { sh1[w] = s1; sh2[w] = s2; }
    __syncthreads();
    float t1 = 0.f, t2 = 0.f;
    #pragma unroll
    for (int i = 0; i < 8; i++) { t1 += sh1[i]; t2 += sh2[i]; }
    float mean = t1 * (1.0f / CDIM);
    float var  = t2 * (1.0f / CDIM) - mean * mean;
    float rstd = rsqrtf(var + 1e-5f);
    float o = (v - mean) * rstd * g[c] + b[c];
    __nv_bfloat16 h, l; bf16split(o, h, l);
    oh[(size_t)row * CDIM + c] = h;
    ol[(size_t)row * CDIM + c] = l;
}

// ---------------- mma.sync bf16x3 GEMM ----------------
// MODE 0: plain fp32   2: +bias +residual fp32
// MODE 3: +bias GELU -> bf16 pair   4: +bias -> bf16 pair
#define GBM 128
#define GBN 128
#define GBK 32
#define ROWB 80
#define TILE_B (128 * ROWB)
#define STAGE_B (4 * TILE_B)
#define GSMEM (2 * STAGE_B)             // 81920 bytes

template<int MODE>
__global__ __launch_bounds__(256, 2)
void gemm_mma(const __nv_bfloat16* __restrict__ Ah, const __nv_bfloat16* __restrict__ Al,
              const __nv_bfloat16* __restrict__ Bh, const __nv_bfloat16* __restrict__ Bl,
              const float* __restrict__ bias, const float* __restrict__ res,
              float* __restrict__ outF,
              __nv_bfloat16* __restrict__ outH, __nv_bfloat16* __restrict__ outL,
              int K, int No)
{
    extern __shared__ char smem[];
    uint32_t sU = smem_to_u32(smem);
    int tid  = threadIdx.x;
    int wid  = tid >> 5, lane = tid & 31;
    int warp_m = wid & 3, warp_n = wid >> 2;
    int m0 = blockIdx.y * GBM, n0 = blockIdx.x * GBN;

    float C[2][8][4];
    #pragma unroll
    for (int mt = 0; mt < 2; mt++)
        #pragma unroll
        for (int nt = 0; nt < 8; nt++)
            #pragma unroll
            for (int k = 0; k < 4; k++) C[mt][nt][k] = 0.f;

    int lr0 = tid >> 2,  lc0 = (tid & 3);
    int lr1 = (tid + 256) >> 2, lc1 = ((tid + 256) & 3);

    int nch = K >> 5;
    auto load_stage = [&](int ch, int buf) {
        int k0 = ch * GBK;
        uint32_t sb = sU + buf * STAGE_B;
        {
            uint32_t so = lr0 * ROWB + lc0 * 16;
            cp16(sb + so,              Ah + (size_t)(m0 + lr0) * K + k0 + lc0 * 8);
            cp16(sb + TILE_B + so,     Al + (size_t)(m0 + lr0) * K + k0 + lc0 * 8);
            cp16(sb + 2 * TILE_B + so, Bh + (size_t)(n0 + lr0) * K + k0 + lc0 * 8);
            cp16(sb + 3 * TILE_B + so, Bl + (size_t)(n0 + lr0) * K + k0 + lc0 * 8);
        }
        {
            uint32_t so = lr1 * ROWB + lc1 * 16;
            cp16(sb + so,              Ah + (size_t)(m0 + lr1) * K + k0 + lc1 * 8);
            cp16(sb + TILE_B + so,     Al + (size_t)(m0 + lr1) * K + k0 + lc1 * 8);
            cp16(sb + 2 * TILE_B + so, Bh + (size_t)(n0 + lr1) * K + k0 + lc1 * 8);
            cp16(sb + 3 * TILE_B + so, Bl + (size_t)(n0 + lr1) * K + k0 + lc1 * 8);
        }
    };

    load_stage(0, 0);
    CP_COMMIT();

    int rin = lane & 7;
    int amat = lane >> 3;
    int bnt  = (lane >> 4) & 1;
    int bkh  = (lane >> 3) & 1;

    for (int ch = 0; ch < nch; ch++) {
        int buf = ch & 1;
        if (ch + 1 < nch) load_stage(ch + 1, buf ^ 1);
        CP_COMMIT();
        CP_WAIT1();
        __syncthreads();

        uint32_t sA  = sU + buf * STAGE_B;
        uint32_t sAl = sA + TILE_B;
        uint32_t sBh = sA + 2 * TILE_B;
        uint32_t sBl = sA + 3 * TILE_B;

        #pragma unroll
        for (int s = 0; s < 2; s++) {
            uint32_t ah[2][4], al[2][4];
            #pragma unroll
            for (int mt = 0; mt < 2; mt++) {
                int row = warp_m * 32 + mt * 16 + (amat & 1) * 8 + rin;
                uint32_t off = row * ROWB + (amat >> 1) * 16 + s * 32;
                ldm4(sA  + off, ah[mt][0], ah[mt][1], ah[mt][2], ah[mt][3]);
                ldm4(sAl + off, al[mt][0], al[mt][1], al[mt][2], al[mt][3]);
            }
            #pragma unroll
            for (int g = 0; g < 4; g++) {
                int row = warp_n * 64 + g * 16 + bnt * 8 + rin;
                uint32_t off = row * ROWB + bkh * 16 + s * 32;
                uint32_t bh[4], bl[4];
                ldm4(sBh + off, bh[0], bh[1], bh[2], bh[3]);
                ldm4(sBl + off, bl[0], bl[1], bl[2], bl[3]);
                #pragma unroll
                for (int mt = 0; mt < 2; mt++) {
                    mma16816(C[mt][2*g],   ah[mt], &bh[0]);
                    mma16816(C[mt][2*g],   ah[mt], &bl[0]);
                    mma16816(C[mt][2*g],   al[mt], &bh[0]);
                    mma16816(C[mt][2*g+1], ah[mt], &bh[2]);
                    mma16816(C[mt][2*g+1], ah[mt], &bl[2]);
                    mma16816(C[mt][2*g+1], al[mt], &bh[2]);
                }
            }
        }
        __syncthreads();
    }
    CP_WAIT0();

    // ---- epilogue ----
    int rbase = m0 + warp_m * 32;
    int cbase = n0 + warp_n * 64;
    #pragma unroll
    for (int mt = 0; mt < 2; mt++) {
        #pragma unroll
        for (int nt = 0; nt < 8; nt++) {
            int row = rbase + mt * 16 + (lane >> 2);
            int col = cbase + nt * 8 + (lane & 3) * 2;
            const float* c = C[mt][nt];
            float2 b2 = make_float2(0.f, 0.f);
            if (MODE >= 2) b2 = *(const float2*)(bias + col);
            if (MODE == 3 || MODE == 4) {
                float g0 = c[0] + b2.x, g1 = c[1] + b2.y;
                float g2 = c[2] + b2.x, g3 = c[3] + b2.y;
                if (MODE == 3) { g0 = gelu_f(g0); g1 = gelu_f(g1); g2 = gelu_f(g2); g3 = gelu_f(g3); }
                uint32_t hi, lo;
                bfpack2(g0, g1, hi, lo);
                *(uint32_t*)(outH + (size_t)row * No + col) = hi;
                *(uint32_t*)(outL + (size_t)row * No + col) = lo;
                bfpack2(g2, g3, hi, lo);
                *(uint32_t*)(outH + (size_t)(row + 8) * No + col) = hi;
                *(uint32_t*)(outL + (size_t)(row + 8) * No + col) = lo;
            } else {
                float2 v0 = make_float2(c[0] + b2.x, c[1] + b2.y);
                float2 v1 = make_float2(c[2] + b2.x, c[3] + b2.y);
                if (MODE == 2) {
                    float2 r0 = *(const float2*)(res + (size_t)row * No + col);
                    float2 r1 = *(const float2*)(res + (size_t)(row + 8) * No + col);
                    v0.x += r0.x; v0.y += r0.y; v1.x += r1.x; v1.y += r1.y;
                }
                *(float2*)(outF + (size_t)row * No + col) = v0;
                *(float2*)(outF + (size_t)(row + 8) * No + col) = v1;
            }
        }
    }
}

// ---------------- flash attention on mma.sync (bf16 hi/lo 3-term) ----------------
// CTA: 128 threads (4 warps), 64 queries (warp w: rows w*16..+15), K-tiles of 64.
#define AP 80                    // smem row pitch (bank-conflict-free ldmatrix)
#define ATILE (64 * AP)          // 5120 bytes per 64x32 bf16 tile

__global__ __launch_bounds__(128)
void attn_mma(const __nv_bfloat16* __restrict__ qkvH,
              const __nv_bfloat16* __restrict__ qkvL,
              __nv_bfloat16* __restrict__ yh, __nv_bfloat16* __restrict__ yl)
{
    __shared__ __align__(16) char sm[4 * ATILE];
    uint32_t sK = smem_to_u32(sm);          // Kh, Kl, Vh, Vl at +0,+1,+2,+3 ATILE
    int tid = threadIdx.x, wid = tid >> 5, lane = tid & 31;
    int b = blockIdx.y >> 3, h = blockIdx.y & 7;
    int q0 = blockIdx.x * 64;
    size_t tokbase = (size_t)b * TSEQ * 768;
    const float qs = 0.17677669529663687f * 1.4426950408889634f;   // 1/sqrt(32)*log2e

    // ---- load Q tile (64x32 hi/lo) into first two buffers, extract A-frags ----
    #pragma unroll
    for (int i = 0; i < 2; i++) {
        int u = tid + i * 128;               // 256 chunks of 16B
        int row = u >> 2, c = u & 3;
        size_t g = tokbase + (size_t)(q0 + row) * 768 + h * DHEAD + c * 8;
        *(uint4*)(sm + row * AP + c * 16)         = *(const uint4*)(qkvH + g);
        *(uint4*)(sm + ATILE + row * AP + c * 16) = *(const uint4*)(qkvL + g);
    }
    __syncthreads();
    uint32_t qh[2][4], ql[2][4];
    #pragma unroll
    for (int ks = 0; ks < 2; ks++) {
        uint32_t a = sK + (wid * 16 + (lane & 15)) * AP + ks * 32 + (lane >> 4) * 16;
        ldm4(a,         qh[ks][0], qh[ks][1], qh[ks][2], qh[ks][3]);
        ldm4(a + ATILE, ql[ks][0], ql[ks][1], ql[ks][2], ql[ks][3]);
    }

    float O[4][4];
    #pragma unroll
    for (int i = 0; i < 4; i++)
        #pragma unroll
        for (int j = 0; j < 4; j++) O[i][j] = 0.f;
    float m0 = -1e30f, m1 = -1e30f, l0 = 0.f, l1 = 0.f;

    int ntiles = blockIdx.x + 1;
    for (int kb = 0; kb < ntiles; kb++) {
        int j0 = kb * 64;
        __syncthreads();                    // previous tile fully consumed
        // ---- async-load K/V hi/lo (4 x 64x32 tiles) ----
        #pragma unroll
        for (int i = 0; i < 8; i++) {
            int u = i * 128 + tid;          // 1024 chunks
            int bufi = u >> 8;
            int c = u & 255, row = c >> 2, cc = c & 3;
            size_t g = tokbase + (size_t)(j0 + row) * 768 + h * DHEAD + cc * 8;
            const __nv_bfloat16* src;
            if      (bufi == 0) src = qkvH + g + CDIM;          // Kh
            else if (bufi == 1) src = qkvL + g + CDIM;          // Kl
            else if (bufi == 2) src = qkvH + g + 2 * CDIM;      // Vh
            else                src = qkvL + g + 2 * CDIM;      // Vl
            cp16(sK + bufi * ATILE + row * AP + cc * 16, src);
        }
        CP_COMMIT(); CP_WAIT0();
        __syncthreads();

        // ---- S = Q K^T (bf16x3) ----
        float sc[8][4];
        #pragma unroll
        for (int nt = 0; nt < 8; nt++)
            #pragma unroll
            for (int j = 0; j < 4; j++) sc[nt][j] = 0.f;
        #pragma unroll
        for (int ks = 0; ks < 2; ks++) {
            #pragma unroll
            for (int g = 0; g < 4; g++) {
                uint32_t addr = sK + (g * 16 + ((lane >> 4) & 1) * 8 + (lane & 7)) * AP
                              + ks * 32 + ((lane >> 3) & 1) * 16;
                uint32_t kh[4], kl[4];
                ldm4(addr,         kh[0], kh[1], kh[2], kh[3]);
                ldm4(addr + ATILE, kl[0], kl[1], kl[2], kl[3]);
                mma16816(sc[2*g],   qh[ks], &kh[0]);
                mma16816(sc[2*g],   qh[ks], &kl[0]);
                mma16816(sc[2*g],   ql[ks], &kh[0]);
                mma16816(sc[2*g+1], qh[ks], &kh[2]);
                mma16816(sc[2*g+1], qh[ks], &kl[2]);
                mma16816(sc[2*g+1], ql[ks], &kh[2]);
            }
        }

        // ---- causal mask on the diagonal tile ----
        if (kb == blockIdx.x) {
            int qr = wid * 16 + (lane >> 2);
            #pragma unroll
            for (int nt = 0; nt < 8; nt++) {
                int kc = nt * 8 + (lane & 3) * 2;
                if (kc     > qr)     sc[nt][0] = -1e30f;
                if (kc + 1 > qr)     sc[nt][1] = -1e30f;
                if (kc     > qr + 8) sc[nt][2] = -1e30f;
                if (kc + 1 > qr + 8) sc[nt][3] = -1e30f;
            }
        }

        // ---- online softmax (base-2, scale folded via fma) ----
        float rm0 = -1e30f, rm1 = -1e30f;
        #pragma unroll
        for (int nt = 0; nt < 8; nt++) {
            rm0 = fmaxf(rm0, fmaxf(sc[nt][0], sc[nt][1]));
            rm1 = fmaxf(rm1, fmaxf(sc[nt][2], sc[nt][3]));
        }
        rm0 = fmaxf(rm0, __shfl_xor_sync(0xFFFFFFFFu, rm0, 1));
        rm0 = fmaxf(rm0, __shfl_xor_sync(0xFFFFFFFFu, rm0, 2));
        rm1 = fmaxf(rm1, __shfl_xor_sync(0xFFFFFFFFu, rm1, 1));
        rm1 = fmaxf(rm1, __shfl_xor_sync(0xFFFFFFFFu, rm1, 2));
        float m0n = fmaxf(m0, rm0), m1n = fmaxf(m1, rm1);
        float c0 = ex2f((m0 - m0n) * qs), c1 = ex2f((m1 - m1n) * qs);
        m0 = m0n; m1 = m1n;
        float mq0 = m0 * qs, mq1 = m1 * qs;
        float rs0 = 0.f, rs1 = 0.f;
        #pragma unroll
        for (int nt = 0; nt < 8; nt++) {
            sc[nt][0] = ex2f(fmaf(sc[nt][0], qs, -mq0));
            sc[nt][1] = ex2f(fmaf(sc[nt][1], qs, -mq0));
            sc[nt][2] = ex2f(fmaf(sc[nt][2], qs, -mq1));
            sc[nt][3] = ex2f(fmaf(sc[nt][3], qs, -mq1));
            rs0 += sc[nt][0] + sc[nt][1];
            rs1 += sc[nt][2] + sc[nt][3];
        }
        rs0 += __shfl_xor_sync(0xFFFFFFFFu, rs0, 1);
        rs0 += __shfl_xor_sync(0xFFFFFFFFu, rs0, 2);
        rs1 += __shfl_xor_sync(0xFFFFFFFFu, rs1, 1);
        rs1 += __shfl_xor_sync(0xFFFFFFFFu, rs1, 2);
        l0 = l0 * c0 + rs0;
        l1 = l1 * c1 + rs1;
        #pragma unroll
        for (int nt = 0; nt < 4; nt++) {
            O[nt][0] *= c0; O[nt][1] *= c0;
            O[nt][2] *= c1; O[nt][3] *= c1;
        }

        // ---- O += P V (Ph*Vh + Ph*Vl + Pl*Vh) ----
        #pragma unroll
        for (int ks = 0; ks < 4; ks++) {
            uint32_t ph[4], pl[4];
            bfpack2(sc[2*ks][0],   sc[2*ks][1],   ph[0], pl[0]);
            bfpack2(sc[2*ks][2],   sc[2*ks][3],   ph[1], pl[1]);
            bfpack2(sc[2*ks+1][0], sc[2*ks+1][1], ph[2], pl[2]);
            bfpack2(sc[2*ks+1][2], sc[2*ks+1][3], ph[3], pl[3]);
            #pragma unroll
            for (int g = 0; g < 2; g++) {
                uint32_t addr = sK + 2 * ATILE
                              + (16 * ks + ((lane >> 3) & 1) * 8 + (lane & 7)) * AP
                              + g * 32 + (lane >> 4) * 16;
                uint32_t vh[4], vl[4];
                ldm4t(addr,         vh[0], vh[1], vh[2], vh[3]);
                ldm4t(addr + ATILE, vl[0], vl[1], vl[2], vl[3]);
                mma16816(O[2*g],   ph, &vh[0]);
                mma16816(O[2*g],   ph, &vl[0]);
                mma16816(O[2*g],   pl, &vh[0]);
                mma16816(O[2*g+1], ph, &vh[2]);
                mma16816(O[2*g+1], ph, &vl[2]);
                mma16816(O[2*g+1], pl, &vh[2]);
            }
        }
    }

    // ---- normalize + write bf16 hi/lo ----
    float i0 = 1.0f / l0, i1 = 1.0f / l1;
    int r0 = q0 + wid * 16 + (lane >> 2);
    #pragma unroll
    for (int nt = 0; nt < 4; nt++) {
        int col = h * DHEAD + nt * 8 + (lane & 3) * 2;
        size_t g0 = (size_t)(b * TSEQ + r0) * CDIM + col;
        size_t g1 = g0 + (size_t)8 * CDIM;
        uint32_t hi, lo;
        bfpack2(O[nt][0] * i0, O[nt][1] * i0, hi, lo);
        *(uint32_t*)(yh + g0) = hi;
        *(uint32_t*)(yl + g0) = lo;
        bfpack2(O[nt][2] * i1, O[nt][3] * i1, hi, lo);
        *(uint32_t*)(yh + g1) = hi;
        *(uint32_t*)(yl + g1) = lo;
    }
}

// ---------------- host orchestration (graph-capturable) ----------------
extern "C" void kernel_launch(void* const* d_in, const int* in_sizes, int n_in,
                              void* d_out, int out_size) {
    (void)in_sizes; (void)n_in; (void)out_size;
    const int*   idx   = (const int*)  d_in[0];
    const float* tok   = (const float*)d_in[1];
    const float* pos   = (const float*)d_in[2];
    const float* ln1g  = (const float*)d_in[3];
    const float* ln1b  = (const float*)d_in[4];
    const float* wqkv  = (const float*)d_in[5];
    const float* bqkv  = (const float*)d_in[6];
    const float* wo    = (const float*)d_in[7];
    const float* bo    = (const float*)d_in[8];
    const float* ln2g  = (const float*)d_in[9];
    const float* ln2b  = (const float*)d_in[10];
    const float* wfc   = (const float*)d_in[11];
    const float* bfc   = (const float*)d_in[12];
    const float* wpr   = (const float*)d_in[13];
    const float* bpr   = (const float*)d_in[14];
    const float* lnfg  = (const float*)d_in[15];
    const float* lnfb  = (const float*)d_in[16];
    const float* wlm   = (const float*)d_in[17];
    float* out = (float*)d_out;

    float *x;
    __nv_bfloat16 *qh, *ql_, *hh, *hl, *yh, *yl, *gh, *gl;
    __nv_bfloat16 *wqkvTh, *wqkvTl, *woTh, *woTl, *wfcTh, *wfcTl, *wprTh, *wprTl, *wlmTh, *wlmTl;
    cudaGetSymbolAddress((void**)&x,   g_x);
    cudaGetSymbolAddress((void**)&qh,  g_qkvh);
    cudaGetSymbolAddress((void**)&ql_, g_qkvl);
    cudaGetSymbolAddress((void**)&hh,  g_hh);
    cudaGetSymbolAddress((void**)&hl,  g_hl);
    cudaGetSymbolAddress((void**)&yh,  g_yh);
    cudaGetSymbolAddress((void**)&yl,  g_yl);
    cudaGetSymbolAddress((void**)&gh,  g_gh);
    cudaGetSymbolAddress((void**)&gl,  g_gl);
    cudaGetSymbolAddress((void**)&wqkvTh, g_wqkvT_h);
    cudaGetSymbolAddress((void**)&wqkvTl, g_wqkvT_l);
    cudaGetSymbolAddress((void**)&woTh,   g_woT_h);
    cudaGetSymbolAddress((void**)&woTl,   g_woT_l);
    cudaGetSymbolAddress((void**)&wfcTh,  g_wfcT_h);
    cudaGetSymbolAddress((void**)&wfcTl,  g_wfcT_l);
    cudaGetSymbolAddress((void**)&wprTh,  g_wprT_h);
    cudaGetSymbolAddress((void**)&wprTl,  g_wprT_l);
    cudaGetSymbolAddress((void**)&wlmTh,  g_wlmT_h);
    cudaGetSymbolAddress((void**)&wlmTl,  g_wlmT_l);

    cudaFuncSetAttribute(gemm_mma<0>, cudaFuncAttributeMaxDynamicSharedMemorySize, GSMEM);
    cudaFuncSetAttribute(gemm_mma<2>, cudaFuncAttributeMaxDynamicSharedMemorySize, GSMEM);
    cudaFuncSetAttribute(gemm_mma<3>, cudaFuncAttributeMaxDynamicSharedMemorySize, GSMEM);
    cudaFuncSetAttribute(gemm_mma<4>, cudaFuncAttributeMaxDynamicSharedMemorySize, GSMEM);

    wsplit_all<<<WS_TOTAL, dim3(32, 8)>>>(
        wqkv, wo, wfc, wpr, wlm,
        wqkvTh, wqkvTl, woTh, woTl, wfcTh, wfcTl, wprTh, wprTl, wlmTh, wlmTl);

    embed_kernel<<<(NTOK * CDIM + 255) / 256, 256>>>(idx, tok, pos, x);

    dim3 gB(256);
    dim3 grid_qkv(3 * CDIM / GBN, NTOK / GBM);
    dim3 grid_prj(CDIM / GBN,     NTOK / GBM);
    dim3 grid_fc (FFDIM / GBN,    NTOK / GBM);
    dim3 grid_lm (VDIM / GBN,     NTOK / GBM);
    dim3 grid_att(TSEQ / 64, BATCH * HEADS);

    for (int l = 0; l < LAYERS; l++) {
        ln_kernel<<<NTOK, 256>>>(x, ln1g + l * CDIM, ln1b + l * CDIM, hh, hl);
        gemm_mma<4><<<grid_qkv, gB, GSMEM>>>(
            hh, hl,
            wqkvTh + (size_t)l * 3 * CDIM * CDIM, wqkvTl + (size_t)l * 3 * CDIM * CDIM,
            bqkv + (size_t)l * 3 * CDIM, nullptr, nullptr, qh, ql_,
            CDIM, 3 * CDIM);
        attn_mma<<<grid_att, 128>>>(qh, ql_, yh, yl);
        gemm_mma<2><<<grid_prj, gB, GSMEM>>>(
            yh, yl,
            woTh + (size_t)l * CDIM * CDIM, woTl + (size_t)l * CDIM * CDIM,
            bo + (size_t)l * CDIM, x, x, nullptr, nullptr,
            CDIM, CDIM);
        ln_kernel<<<NTOK, 256>>>(x, ln2g + l * CDIM, ln2b + l * CDIM, hh, hl);
        gemm_mma<3><<<grid_fc, gB, GSMEM>>>(
            hh, hl,
            wfcTh + (size_t)l * FFDIM * CDIM, wfcTl + (size_t)l * FFDIM * CDIM,
            bfc + (size_t)l * FFDIM, nullptr, nullptr, gh, gl,
            CDIM, FFDIM);
        gemm_mma<2><<<grid_prj, gB, GSMEM>>>(
            gh, gl,
            wprTh + (size_t)l * CDIM * FFDIM, wprTl + (size_t)l * CDIM * FFDIM,
            bpr + (size_t)l * CDIM, x, x, nullptr, nullptr,
            FFDIM, CDIM);
    }

    ln_kernel<<<NTOK, 256>>>(x, lnfg, lnfb, hh, hl);
    gemm_mma<0><<<grid_lm, gB, GSMEM>>>(
        hh, hl, wlmTh, wlmTl,
        nullptr, nullptr, out, nullptr, nullptr,
        CDIM, VDIM);
}